// round 10
// baseline (speedup 1.0000x reference)
#include <cuda_runtime.h>
#include <cuda_fp16.h>
#include <math.h>
#include <stdint.h>

#define B_   2
#define S_   2048
#define H_   4096
#define NH_  32
#define NKV_ 8
#define HD_  128
#define TOK  (B_*S_)        // 4096
#define QWN  (NH_*HD_*H_)   // 16777216
#define KWN  (NKV_*HD_*H_)  // 4194304

// ---------------- scratch (static device globals; no allocation) ----------
__device__ float g_cos[S_*64];
__device__ float g_sin[S_*64];

// fp16 operands
__device__ __half g_hsH[(size_t)TOK*H_], g_hsL[(size_t)TOK*H_];
__device__ __half g_Wq[(size_t)QWN];
__device__ __half g_Wk[(size_t)KWN];
__device__ __half g_Wv[(size_t)KWN];
__device__ __half g_Wo[(size_t)H_*H_];
__device__ __half g_OH[(size_t)TOK*H_], g_OL[(size_t)TOK*H_];

// attention operands (fp16; RoPE and scale pre-applied)
__device__ __half g_QbH[(size_t)B_*NH_*S_*HD_], g_QbL[(size_t)B_*NH_*S_*HD_];
__device__ __half g_Kb[(size_t)B_*NKV_*S_*HD_];
__device__ __half g_Vb[(size_t)B_*NKV_*S_*HD_];

// ---------------- helpers ----------------------------------------------------
__device__ __forceinline__ uint32_t smem_to_u32(const void* p){
    uint32_t a;
    asm("{ .reg .u64 t; cvta.to.shared.u64 t, %1; cvt.u32.u64 %0, t; }" : "=r"(a) : "l"(p));
    return a;
}
#define CP_ASYNC16(dst, src) \
    asm volatile("cp.async.cg.shared.global [%0], [%1], 16;" :: "r"(dst), "l"(src))
#define CP_COMMIT() asm volatile("cp.async.commit_group;" ::: "memory")
#define CP_WAIT1()  asm volatile("cp.async.wait_group 1;" ::: "memory")
#define CP_WAIT0()  asm volatile("cp.async.wait_group 0;" ::: "memory")

#define LDSM_X4(r, addr) \
    asm volatile("ldmatrix.sync.aligned.m8n8.x4.shared.b16 {%0,%1,%2,%3}, [%4];" \
        : "=r"((r)[0]),"=r"((r)[1]),"=r"((r)[2]),"=r"((r)[3]) : "r"(addr))
#define LDSM_X4_T(r, addr) \
    asm volatile("ldmatrix.sync.aligned.m8n8.x4.trans.shared.b16 {%0,%1,%2,%3}, [%4];" \
        : "=r"((r)[0]),"=r"((r)[1]),"=r"((r)[2]),"=r"((r)[3]) : "r"(addr))

#define MMA_F16(c, a, b0, b1) \
    asm volatile("mma.sync.aligned.m16n8k16.row.col.f32.f16.f16.f32 " \
        "{%0,%1,%2,%3},{%4,%5,%6,%7},{%8,%9},{%0,%1,%2,%3};" \
        : "+f"((c)[0]),"+f"((c)[1]),"+f"((c)[2]),"+f"((c)[3]) \
        : "r"((a)[0]),"r"((a)[1]),"r"((a)[2]),"r"((a)[3]), "r"(b0),"r"(b1))

__device__ __forceinline__ uint32_t f2h2(float x, float y){
    __half2 h = __floats2half2_rn(x, y);
    return *(uint32_t*)&h;
}
__device__ __forceinline__ void split_pair_h(float x, float y, uint32_t& h2, uint32_t& l2){
    h2 = f2h2(x, y);
    float2 f = __half22float2(*(__half2*)&h2);
    l2 = f2h2(x - f.x, y - f.y);
}
// fast e^x on FMA/ALU pipes. valid for x <= 0, clamps below -87. fast_exp(0)==1.0f exactly.
__device__ __forceinline__ float fast_exp(float x){
    x = fmaxf(x, -87.0f);
    float y = x * 1.4426950408889634f;
    float r = __fadd_rn(y, 12582912.0f);
    float f = y - __fadd_rn(r, -12582912.0f);
    float p = 1.5403530e-4f;
    p = __fmaf_rn(p, f, 1.3333558e-3f);
    p = __fmaf_rn(p, f, 9.6181291e-3f);
    p = __fmaf_rn(p, f, 5.5504109e-2f);
    p = __fmaf_rn(p, f, 2.4022651e-1f);
    p = __fmaf_rn(p, f, 6.9314718e-1f);
    p = __fmaf_rn(p, f, 1.0f);
    int n = __float_as_int(r) - 0x4B400000;
    return __int_as_float(__float_as_int(p) + (n << 23));
}

// ---------------- rope tables ----------------------------------------------
__global__ void rope_tables_kernel(){
    int idx = blockIdx.x * blockDim.x + threadIdx.x;
    if (idx >= S_*64) return;
    int s = idx >> 6, j = idx & 63;
    double inv = pow(500000.0, -((double)j)/64.0);
    float ang = (float)s * (float)inv;
    g_cos[idx] = (float)cos((double)ang);
    g_sin[idx] = (float)sin((double)ang);
}

// ---------------- fp32 -> fp16 hi/lo split (hidden states), 8 floats/thread --
__global__ void split_hs_kernel(const float* __restrict__ src){
    size_t i = (((size_t)blockIdx.x << 8) + threadIdx.x) << 3;
    #pragma unroll
    for (int u = 0; u < 2; ++u){
        float4 v = *(const float4*)(src + i + u*4);
        uint32_t h0, l0, h1, l1;
        split_pair_h(v.x, v.y, h0, l0);
        split_pair_h(v.z, v.w, h1, l1);
        *(uint32_t*)(g_hsH + i + u*4)     = h0;
        *(uint32_t*)(g_hsH + i + u*4 + 2) = h1;
        *(uint32_t*)(g_hsL + i + u*4)     = l0;
        *(uint32_t*)(g_hsL + i + u*4 + 2) = l1;
    }
}

// ---------------- all weights fp32 -> fp16, one kernel, 8 floats/thread -----
__global__ void convert_weights_kernel(const float* __restrict__ Wq, const float* __restrict__ Wk,
                                       const float* __restrict__ Wv, const float* __restrict__ Wo){
    size_t i = (((size_t)blockIdx.x << 8) + threadIdx.x) << 3;
    const float* src; __half* dst; size_t off;
    if (i < QWN)              { src = Wq; dst = g_Wq; off = i; }
    else if (i < QWN + KWN)   { src = Wk; dst = g_Wk; off = i - QWN; }
    else if (i < QWN + 2*KWN) { src = Wv; dst = g_Wv; off = i - QWN - KWN; }
    else                      { src = Wo; dst = g_Wo; off = i - QWN - 2*KWN; }
    #pragma unroll
    for (int u = 0; u < 2; ++u){
        float4 v = *(const float4*)(src + off + u*4);
        *(uint32_t*)(dst + off + u*4)     = f2h2(v.x, v.y);
        *(uint32_t*)(dst + off + u*4 + 2) = f2h2(v.z, v.w);
    }
}

// ---------------- HMMA GEMM (fused QKV / O-proj), fp16 2-pass, 3-stage ------
// BM=128 BN=128 BK=32; 8 warps (4x2); 3-stage cp.async; 2 CTAs/SM.
#define BK_      32
#define ROWB     80
#define MATB     (128*ROWB)             // 10240
#define STGB     (3*MATB)               // 30720 (AH, AL, BH)
#define GSMEM    (3*STGB)               // 92160 (also covers 67584B epilogue staging)
#define KTILES   (H_/BK_)               // 128

__device__ __forceinline__ void hmma_load_stage(
    uint32_t sb, int s, const __half* AH, const __half* AL, const __half* BH,
    int M0, int N0, int kt, int tid)
{
    uint32_t base = sb + s*STGB;
    #pragma unroll
    for (int i = 0; i < 6; ++i){
        int c = tid + (i << 8);          // 0..1535
        int mat = c >> 9;                // 0=AH 1=AL 2=BH
        int cc = c & 511;
        int row = cc >> 2, ch = cc & 3;
        uint32_t soff = (uint32_t)mat*MATB + row*ROWB + (ch << 4);
        const __half* src = (mat == 0) ? AH : (mat == 1) ? AL : BH;
        int base_row = (mat == 2) ? N0 : M0;
        CP_ASYNC16(base + soff, src + (size_t)(base_row + row)*H_ + kt*BK_ + (ch << 3));
    }
}

// mode 0: fused QKV projections (blockIdx.x: 0-31 Q, 32-39 K, 40-47 V)
// mode 1: O projection -> Cout fp32
__global__ __launch_bounds__(256, 2)
void gemm_hmma_kernel(float* __restrict__ Cout, int mode)
{
    extern __shared__ char smem[];
    uint32_t sb = smem_to_u32(smem);
    const int tid = threadIdx.x;
    const int wid = tid >> 5, lane = tid & 31;
    const int wm = wid & 3, wn = wid >> 2;
    const int bx = blockIdx.x;
    const int M0 = blockIdx.y << 7;

    const __half *AH, *AL, *BH;
    int N0, dest, head = 0;
    if (mode == 1){
        AH = g_OH; AL = g_OL; BH = g_Wo;
        N0 = bx << 7; dest = 3;
    } else {
        AH = g_hsH; AL = g_hsL;
        if (bx < 32)      { BH = g_Wq; head = bx;      dest = 0; }
        else if (bx < 40) { BH = g_Wk; head = bx - 32; dest = 1; }
        else              { BH = g_Wv; head = bx - 40; dest = 2; }
        N0 = head << 7;
    }

    float acc[2][8][4];
    #pragma unroll
    for (int m = 0; m < 2; ++m)
        #pragma unroll
        for (int n = 0; n < 8; ++n)
            #pragma unroll
            for (int j = 0; j < 4; ++j) acc[m][n][j] = 0.f;

    hmma_load_stage(sb, 0, AH, AL, BH, M0, N0, 0, tid); CP_COMMIT();
    hmma_load_stage(sb, 1, AH, AL, BH, M0, N0, 1, tid); CP_COMMIT();

    const uint32_t aRow = (uint32_t)(wm*32 + (lane & 15));
    const uint32_t aColB = (uint32_t)(((lane >> 4) << 3) * 2);
    const uint32_t bRow = (uint32_t)(wn*64 + ((lane & 7) | ((lane & 16) >> 1)));
    const uint32_t bColB = (uint32_t)((((lane >> 3) & 1) << 3) * 2);

    #pragma unroll 1
    for (int kt = 0; kt < KTILES; ++kt){
        const int s = kt % 3;
        if (kt < KTILES - 1) { CP_WAIT1(); } else { CP_WAIT0(); }
        __syncthreads();
        if (kt + 2 < KTILES)
            hmma_load_stage(sb, (kt + 2) % 3, AH, AL, BH, M0, N0, kt + 2, tid);
        CP_COMMIT();

        const uint32_t stA = sb + s*STGB;
        const uint32_t stB = stA + 2*MATB;
        #pragma unroll
        for (int ks = 0; ks < 2; ++ks){
            const uint32_t kB = (uint32_t)(ks << 5);
            uint32_t aHr[2][4], aLr[2][4];
            #pragma unroll
            for (int mm = 0; mm < 2; ++mm){
                uint32_t off = (aRow + mm*16)*ROWB + kB + aColB;
                LDSM_X4(aHr[mm], stA + off);
                LDSM_X4(aLr[mm], stA + MATB + off);
            }
            #pragma unroll
            for (int g = 0; g < 4; ++g){
                uint32_t bH[4];
                uint32_t off = (bRow + g*16)*ROWB + kB + bColB;
                LDSM_X4(bH, stB + off);
                MMA_F16(acc[0][2*g],   aHr[0], bH[0], bH[1]);
                MMA_F16(acc[0][2*g+1], aHr[0], bH[2], bH[3]);
                MMA_F16(acc[1][2*g],   aHr[1], bH[0], bH[1]);
                MMA_F16(acc[1][2*g+1], aHr[1], bH[2], bH[3]);
                MMA_F16(acc[0][2*g],   aLr[0], bH[0], bH[1]);
                MMA_F16(acc[0][2*g+1], aLr[0], bH[2], bH[3]);
                MMA_F16(acc[1][2*g],   aLr[1], bH[0], bH[1]);
                MMA_F16(acc[1][2*g+1], aLr[1], bH[2], bH[3]);
            }
        }
    }

    // ---- epilogue ----
    const int rbase = wm*32 + (lane >> 2);
    const int cbase = wn*64 + (lane & 3)*2;
    if (dest == 3 || dest == 2){
        #pragma unroll
        for (int mm = 0; mm < 2; ++mm){
            #pragma unroll
            for (int half = 0; half < 2; ++half){
                int r = M0 + rbase + mm*16 + half*8;
                #pragma unroll
                for (int nn = 0; nn < 8; ++nn){
                    float vx = acc[mm][nn][half*2];
                    float vy = acc[mm][nn][half*2 + 1];
                    if (dest == 3){
                        float2 v; v.x = vx; v.y = vy;
                        *(float2*)(Cout + (size_t)r*H_ + N0 + cbase + nn*8) = v;
                    } else {
                        int bb = r >> 11, ss = r & (S_ - 1);
                        size_t idx = (((size_t)bb*NKV_ + head)*S_ + ss)*HD_ + cbase + nn*8;
                        *(uint32_t*)(g_Vb + idx) = f2h2(vx, vy);
                    }
                }
            }
        }
    } else {
        // Q or K: stage tile in smem, apply RoPE (+scale for Q), write fp16 (paired 4B stores)
        __syncthreads();
        float* sm32 = (float*)smem;
        #pragma unroll
        for (int mm = 0; mm < 2; ++mm){
            #pragma unroll
            for (int half = 0; half < 2; ++half){
                int rl = rbase + mm*16 + half*8;
                #pragma unroll
                for (int nn = 0; nn < 8; ++nn){
                    float2 v;
                    v.x = acc[mm][nn][half*2];
                    v.y = acc[mm][nn][half*2 + 1];
                    *(float2*)(sm32 + rl*132 + cbase + nn*8) = v;
                }
            }
        }
        __syncthreads();
        const float qsc = 0.08838834764831845f;
        #pragma unroll 4
        for (int i = tid; i < 128*32; i += 256){
            int r = i >> 5, jp = (i & 31) << 1;   // pair of columns jp, jp+1
            int token = M0 + r;
            int bb = token >> 11, ss = token & (S_ - 1);
            float ca = g_cos[(ss << 6) + jp],     sa = g_sin[(ss << 6) + jp];
            float cb = g_cos[(ss << 6) + jp + 1], sb2 = g_sin[(ss << 6) + jp + 1];
            float x1a = sm32[r*132 + jp],      x1b = sm32[r*132 + jp + 1];
            float x2a = sm32[r*132 + jp + 64], x2b = sm32[r*132 + jp + 65];
            float y1a = x1a*ca - x2a*sa,  y1b = x1b*cb - x2b*sb2;
            float y2a = x2a*ca + x1a*sa,  y2b = x2b*cb + x1b*sb2;
            if (dest == 0){
                y1a *= qsc; y1b *= qsc; y2a *= qsc; y2b *= qsc;
                size_t base = (((size_t)bb*NH_ + head)*S_ + ss)*HD_;
                uint32_t h2a, l2a, h2b, l2b;
                split_pair_h(y1a, y1b, h2a, l2a);
                split_pair_h(y2a, y2b, h2b, l2b);
                *(uint32_t*)(g_QbH + base + jp)      = h2a;
                *(uint32_t*)(g_QbH + base + jp + 64) = h2b;
                *(uint32_t*)(g_QbL + base + jp)      = l2a;
                *(uint32_t*)(g_QbL + base + jp + 64) = l2b;
            } else {
                size_t base = (((size_t)bb*NKV_ + head)*S_ + ss)*HD_;
                *(uint32_t*)(g_Kb + base + jp)      = f2h2(y1a, y1b);
                *(uint32_t*)(g_Kb + base + jp + 64) = f2h2(y2a, y2b);
            }
        }
    }
}

// ---------------- HMMA flash attention (fp16 2-pass) -------------------------
// 128 threads, 4 warps, Q-tile 64 rows, KV-tile 64 keys, 2-stage, 2 CTAs/SM.
#define AROWB 272
#define AQMAT (64*AROWB)                // 17408 (Q: 64 rows)
#define AKMAT (64*AROWB)                // 17408
#define ASTGB (2*AKMAT)                 // K + V = 34816
#define ASMEM (2*AQMAT + 2*ASTGB)       // 104448 -> 2 CTAs/SM
#define NKB   (S_/64)                   // 32

__device__ __forceinline__ void attn_load_kv(
    uint32_t st, const __half* Kg, const __half* Vg, int key0, int tid)
{
    #pragma unroll
    for (int i = 0; i < 16; ++i){
        int c = tid + (i << 7);          // 0..2047 (128 threads)
        int mat = c >> 10;               // 0=K 1=V
        int cc = c & 1023;
        int row = cc >> 4, ch = cc & 15;
        uint32_t dst = st + (uint32_t)mat*AKMAT + row*AROWB + (ch << 4);
        const __half* src = mat ? Vg : Kg;
        CP_ASYNC16(dst, src + (size_t)(key0 + row)*HD_ + (ch << 3));
    }
}

__global__ __launch_bounds__(128, 2)
void attn_mma_kernel(){
    extern __shared__ char smem[];
    uint32_t sb = smem_to_u32(smem);
    const int tid = threadIdx.x;
    const int wid = tid >> 5, lane = tid & 31;
    const int qb = blockIdx.x, h = blockIdx.y, b = blockIdx.z;
    const int g = h >> 2;

    const __half* QHg = g_QbH + (((size_t)b*NH_ + h)*S_ + (size_t)qb*64)*HD_;
    const __half* QLg = g_QbL + (((size_t)b*NH_ + h)*S_ + (size_t)qb*64)*HD_;
    const __half* Kg  = g_Kb + ((size_t)b*NKV_ + g)*S_*HD_;
    const __half* Vg  = g_Vb + ((size_t)b*NKV_ + g)*S_*HD_;

    const uint32_t QH0 = sb, QL0 = sb + AQMAT;
    const uint32_t KVB = sb + 2*AQMAT;

    // Q load (64 rows x 128 cols, H+L), 128 threads
    #pragma unroll
    for (int i = 0; i < 16; ++i){
        int c = tid + (i << 7);          // 0..2047
        int mat = c >> 10;               // 0=QH 1=QL
        int cc = c & 1023;
        int row = cc >> 4, ch = cc & 15;
        uint32_t dst = (mat ? QL0 : QH0) + row*AROWB + (ch << 4);
        const __half* src = mat ? QLg : QHg;
        CP_ASYNC16(dst, src + (size_t)row*HD_ + (ch << 3));
    }
    attn_load_kv(KVB, Kg, Vg, 0, tid);
    CP_COMMIT();
    attn_load_kv(KVB + ASTGB, Kg, Vg, 64, tid);
    CP_COMMIT();

    float m0 = -1e30f, m1 = -1e30f, l0 = 0.f, l1 = 0.f;
    float O[16][4];
    #pragma unroll
    for (int nt = 0; nt < 16; ++nt)
        #pragma unroll
        for (int j = 0; j < 4; ++j) O[nt][j] = 0.f;

    const uint32_t aOff  = (uint32_t)(wid*16 + (lane & 15))*AROWB + ((lane >> 4) << 4);
    const uint32_t bOffK = (uint32_t)((lane & 7) | ((lane & 16) >> 1))*AROWB + (((lane >> 3) & 1) << 4);
    const uint32_t vOff  = (uint32_t)((lane & 7) + (lane & 8))*AROWB + ((lane >> 4) << 4);

    #pragma unroll 1
    for (int kb = 0; kb < NKB; ++kb){
        const int s = kb & 1;
        const uint32_t Kst = KVB + s*ASTGB;
        const uint32_t Vst = Kst + AKMAT;

        if (kb < NKB - 1) { CP_WAIT1(); } else { CP_WAIT0(); }
        __syncthreads();

        // ---- S = Q K^T (2-pass fp16) ----
        float Sa[8][4];
        #pragma unroll
        for (int nt = 0; nt < 8; ++nt)
            #pragma unroll
            for (int j = 0; j < 4; ++j) Sa[nt][j] = 0.f;

        #pragma unroll
        for (int ks = 0; ks < 8; ++ks){
            uint32_t aH[4], aL[4];
            LDSM_X4(aH, QH0 + aOff + ks*32);
            LDSM_X4(aL, QL0 + aOff + ks*32);
            #pragma unroll
            for (int gi = 0; gi < 4; ++gi){
                uint32_t bK[4];
                LDSM_X4(bK, Kst + bOffK + gi*(16*AROWB) + ks*32);
                MMA_F16(Sa[2*gi],   aH, bK[0], bK[1]);
                MMA_F16(Sa[2*gi+1], aH, bK[2], bK[3]);
                MMA_F16(Sa[2*gi],   aL, bK[0], bK[1]);
                MMA_F16(Sa[2*gi+1], aL, bK[2], bK[3]);
            }
        }

        // ---- online softmax ----
        float mb0 = -1e30f, mb1 = -1e30f;
        #pragma unroll
        for (int nt = 0; nt < 8; ++nt){
            mb0 = fmaxf(mb0, fmaxf(Sa[nt][0], Sa[nt][1]));
            mb1 = fmaxf(mb1, fmaxf(Sa[nt][2], Sa[nt][3]));
        }
        mb0 = fmaxf(mb0, __shfl_xor_sync(0xffffffffu, mb0, 1));
        mb0 = fmaxf(mb0, __shfl_xor_sync(0xffffffffu, mb0, 2));
        mb1 = fmaxf(mb1, __shfl_xor_sync(0xffffffffu, mb1, 1));
        mb1 = fmaxf(mb1, __shfl_xor_sync(0xffffffffu, mb1, 2));
        float m0n = fmaxf(m0, mb0), m1n = fmaxf(m1, mb1);
        float corr0 = fast_exp(m0 - m0n), corr1 = fast_exp(m1 - m1n);
        m0 = m0n; m1 = m1n;

        float ls0 = 0.f, ls1 = 0.f;
        #pragma unroll
        for (int nt = 0; nt < 8; ++nt){
            Sa[nt][0] = fast_exp(Sa[nt][0] - m0);
            Sa[nt][1] = fast_exp(Sa[nt][1] - m0);
            Sa[nt][2] = fast_exp(Sa[nt][2] - m1);
            Sa[nt][3] = fast_exp(Sa[nt][3] - m1);
            ls0 += Sa[nt][0] + Sa[nt][1];
            ls1 += Sa[nt][2] + Sa[nt][3];
        }
        ls0 += __shfl_xor_sync(0xffffffffu, ls0, 1);
        ls0 += __shfl_xor_sync(0xffffffffu, ls0, 2);
        ls1 += __shfl_xor_sync(0xffffffffu, ls1, 1);
        ls1 += __shfl_xor_sync(0xffffffffu, ls1, 2);
        l0 = l0*corr0 + ls0;
        l1 = l1*corr1 + ls1;

        // skip the rescale when corr == 1 exactly (bit-identical: x*1 == x)
        if (!__all_sync(0xffffffffu, (corr0 == 1.0f) && (corr1 == 1.0f))){
            #pragma unroll
            for (int nt = 0; nt < 16; ++nt){
                O[nt][0] *= corr0; O[nt][1] *= corr0;
                O[nt][2] *= corr1; O[nt][3] *= corr1;
            }
        }

        // ---- P -> A fragments (fp16 hi/lo) ----
        uint32_t aPh[4][4], aPl[4][4];
        #pragma unroll
        for (int kt = 0; kt < 4; ++kt){
            split_pair_h(Sa[2*kt][0],   Sa[2*kt][1],   aPh[kt][0], aPl[kt][0]);
            split_pair_h(Sa[2*kt][2],   Sa[2*kt][3],   aPh[kt][1], aPl[kt][1]);
            split_pair_h(Sa[2*kt+1][0], Sa[2*kt+1][1], aPh[kt][2], aPl[kt][2]);
            split_pair_h(Sa[2*kt+1][2], Sa[2*kt+1][3], aPh[kt][3], aPl[kt][3]);
        }

        // ---- O += P V (2-pass fp16, V via ldmatrix.trans) ----
        #pragma unroll
        for (int kt = 0; kt < 4; ++kt){
            #pragma unroll
            for (int dp = 0; dp < 8; ++dp){
                uint32_t bV[4];
                LDSM_X4_T(bV, Vst + vOff + kt*(16*AROWB) + dp*32);
                MMA_F16(O[2*dp],   aPh[kt], bV[0], bV[1]);
                MMA_F16(O[2*dp+1], aPh[kt], bV[2], bV[3]);
                MMA_F16(O[2*dp],   aPl[kt], bV[0], bV[1]);
                MMA_F16(O[2*dp+1], aPl[kt], bV[2], bV[3]);
            }
        }

        // prefetch kb+2 into this stage (after all warps done reading it)
        __syncthreads();
        if (kb + 2 < NKB){
            attn_load_kv(KVB + s*ASTGB, Kg, Vg, (kb+2)*64, tid);
        }
        CP_COMMIT();
    }

    // ---- epilogue: normalize, fp16 hi/lo to g_OH/g_OL ----
    const float inv0 = 1.0f / l0, inv1 = 1.0f / l1;
    const int s0 = qb*64 + wid*16 + (lane >> 2);
    const size_t ob = (size_t)b*S_*H_ + (size_t)h*HD_;
    #pragma unroll
    for (int nt = 0; nt < 16; ++nt){
        int d = nt*8 + (lane & 3)*2;
        uint32_t h2, l2;
        split_pair_h(O[nt][0]*inv0, O[nt][1]*inv0, h2, l2);
        size_t idx0 = ob + (size_t)s0*H_ + d;
        *(uint32_t*)(g_OH + idx0) = h2;
        *(uint32_t*)(g_OL + idx0) = l2;
        split_pair_h(O[nt][2]*inv1, O[nt][3]*inv1, h2, l2);
        size_t idx1 = ob + (size_t)(s0 + 8)*H_ + d;
        *(uint32_t*)(g_OH + idx1) = h2;
        *(uint32_t*)(g_OL + idx1) = l2;
    }
}

// ---------------- launch ----------------------------------------------------
extern "C" void kernel_launch(void* const* d_in, const int* in_sizes, int n_in,
                              void* d_out, int out_size)
{
    const float* hs = (const float*)d_in[0];
    const float* Wq = (const float*)d_in[1];
    const float* Wk = (const float*)d_in[2];
    const float* Wv = (const float*)d_in[3];
    const float* Wo = (const float*)d_in[4];
    float* out = (float*)d_out;

    rope_tables_kernel<<<(S_*64 + 255)/256, 256>>>();
    split_hs_kernel<<<TOK*H_/(8*256), 256>>>(hs);
    convert_weights_kernel<<<(QWN + 2*KWN + H_*H_)/(8*256), 256>>>(Wq, Wk, Wv, Wo);

    cudaFuncSetAttribute(gemm_hmma_kernel, cudaFuncAttributeMaxDynamicSharedMemorySize, GSMEM);
    cudaFuncSetAttribute(attn_mma_kernel, cudaFuncAttributeMaxDynamicSharedMemorySize, ASMEM);

    // fused Q/K/V projections with RoPE + fp16 conversion in epilogue
    gemm_hmma_kernel<<<dim3(48, 32), 256, GSMEM>>>(nullptr, 0);

    // flash attention (64-row Q tiles, 2 CTAs/SM)
    attn_mma_kernel<<<dim3(S_/64, NH_, B_), 128, ASMEM>>>();

    // output projection -> d_out
    gemm_hmma_kernel<<<dim3(32, 32), 256, GSMEM>>>(out, 1);
}

// round 11
// speedup vs baseline: 1.1269x; 1.1269x over previous
#include <cuda_runtime.h>
#include <cuda_fp16.h>
#include <math.h>
#include <stdint.h>

#define B_   2
#define S_   2048
#define H_   4096
#define NH_  32
#define NKV_ 8
#define HD_  128
#define TOK  (B_*S_)        // 4096
#define QWN  (NH_*HD_*H_)   // 16777216
#define KWN  (NKV_*HD_*H_)  // 4194304

// ---------------- scratch (static device globals; no allocation) ----------
__device__ float g_cos[S_*64];
__device__ float g_sin[S_*64];

// fp16 operands
__device__ __half g_hsH[(size_t)TOK*H_], g_hsL[(size_t)TOK*H_];
__device__ __half g_Wq[(size_t)QWN];
__device__ __half g_Wk[(size_t)KWN];
__device__ __half g_Wv[(size_t)KWN];
__device__ __half g_Wo[(size_t)H_*H_];
__device__ __half g_OH[(size_t)TOK*H_], g_OL[(size_t)TOK*H_];

// attention operands (fp16; RoPE and scale pre-applied)
__device__ __half g_QbH[(size_t)B_*NH_*S_*HD_], g_QbL[(size_t)B_*NH_*S_*HD_];
__device__ __half g_Kb[(size_t)B_*NKV_*S_*HD_];
__device__ __half g_Vb[(size_t)B_*NKV_*S_*HD_];

// ---------------- helpers ----------------------------------------------------
__device__ __forceinline__ uint32_t smem_to_u32(const void* p){
    uint32_t a;
    asm("{ .reg .u64 t; cvta.to.shared.u64 t, %1; cvt.u32.u64 %0, t; }" : "=r"(a) : "l"(p));
    return a;
}
#define CP_ASYNC16(dst, src) \
    asm volatile("cp.async.cg.shared.global [%0], [%1], 16;" :: "r"(dst), "l"(src))
#define CP_COMMIT() asm volatile("cp.async.commit_group;" ::: "memory")
#define CP_WAIT0()  asm volatile("cp.async.wait_group 0;" ::: "memory")

#define LDSM_X4(r, addr) \
    asm volatile("ldmatrix.sync.aligned.m8n8.x4.shared.b16 {%0,%1,%2,%3}, [%4];" \
        : "=r"((r)[0]),"=r"((r)[1]),"=r"((r)[2]),"=r"((r)[3]) : "r"(addr))
#define LDSM_X4_T(r, addr) \
    asm volatile("ldmatrix.sync.aligned.m8n8.x4.trans.shared.b16 {%0,%1,%2,%3}, [%4];" \
        : "=r"((r)[0]),"=r"((r)[1]),"=r"((r)[2]),"=r"((r)[3]) : "r"(addr))

#define MMA_F16(c, a, b0, b1) \
    asm volatile("mma.sync.aligned.m16n8k16.row.col.f32.f16.f16.f32 " \
        "{%0,%1,%2,%3},{%4,%5,%6,%7},{%8,%9},{%0,%1,%2,%3};" \
        : "+f"((c)[0]),"+f"((c)[1]),"+f"((c)[2]),"+f"((c)[3]) \
        : "r"((a)[0]),"r"((a)[1]),"r"((a)[2]),"r"((a)[3]), "r"(b0),"r"(b1))

__device__ __forceinline__ uint32_t f2h2(float x, float y){
    __half2 h = __floats2half2_rn(x, y);
    return *(uint32_t*)&h;
}
__device__ __forceinline__ void split_pair_h(float x, float y, uint32_t& h2, uint32_t& l2){
    h2 = f2h2(x, y);
    float2 f = __half22float2(*(__half2*)&h2);
    l2 = f2h2(x - f.x, y - f.y);
}
// fast e^x on FMA/ALU pipes. valid for x <= 0, clamps below -87. fast_exp(0)==1.0f exactly.
__device__ __forceinline__ float fast_exp(float x){
    x = fmaxf(x, -87.0f);
    float y = x * 1.4426950408889634f;
    float r = __fadd_rn(y, 12582912.0f);
    float f = y - __fadd_rn(r, -12582912.0f);
    float p = 1.5403530e-4f;
    p = __fmaf_rn(p, f, 1.3333558e-3f);
    p = __fmaf_rn(p, f, 9.6181291e-3f);
    p = __fmaf_rn(p, f, 5.5504109e-2f);
    p = __fmaf_rn(p, f, 2.4022651e-1f);
    p = __fmaf_rn(p, f, 6.9314718e-1f);
    p = __fmaf_rn(p, f, 1.0f);
    int n = __float_as_int(r) - 0x4B400000;
    return __int_as_float(__float_as_int(p) + (n << 23));
}

// ---------------- rope tables ----------------------------------------------
__global__ void rope_tables_kernel(){
    int idx = blockIdx.x * blockDim.x + threadIdx.x;
    if (idx >= S_*64) return;
    int s = idx >> 6, j = idx & 63;
    double inv = pow(500000.0, -((double)j)/64.0);
    float ang = (float)s * (float)inv;
    g_cos[idx] = (float)cos((double)ang);
    g_sin[idx] = (float)sin((double)ang);
}

// ---------------- fp32 -> fp16 hi/lo split (hidden states), 8 floats/thread --
__global__ void split_hs_kernel(const float* __restrict__ src){
    size_t i = (((size_t)blockIdx.x << 8) + threadIdx.x) << 3;
    #pragma unroll
    for (int u = 0; u < 2; ++u){
        float4 v = *(const float4*)(src + i + u*4);
        uint32_t h0, l0, h1, l1;
        split_pair_h(v.x, v.y, h0, l0);
        split_pair_h(v.z, v.w, h1, l1);
        *(uint32_t*)(g_hsH + i + u*4)     = h0;
        *(uint32_t*)(g_hsH + i + u*4 + 2) = h1;
        *(uint32_t*)(g_hsL + i + u*4)     = l0;
        *(uint32_t*)(g_hsL + i + u*4 + 2) = l1;
    }
}

// ---------------- all weights fp32 -> fp16, one kernel, 8 floats/thread -----
__global__ void convert_weights_kernel(const float* __restrict__ Wq, const float* __restrict__ Wk,
                                       const float* __restrict__ Wv, const float* __restrict__ Wo){
    size_t i = (((size_t)blockIdx.x << 8) + threadIdx.x) << 3;
    const float* src; __half* dst; size_t off;
    if (i < QWN)              { src = Wq; dst = g_Wq; off = i; }
    else if (i < QWN + KWN)   { src = Wk; dst = g_Wk; off = i - QWN; }
    else if (i < QWN + 2*KWN) { src = Wv; dst = g_Wv; off = i - QWN - KWN; }
    else                      { src = Wo; dst = g_Wo; off = i - QWN - 2*KWN; }
    #pragma unroll
    for (int u = 0; u < 2; ++u){
        float4 v = *(const float4*)(src + off + u*4);
        *(uint32_t*)(dst + off + u*4)     = f2h2(v.x, v.y);
        *(uint32_t*)(dst + off + u*4 + 2) = f2h2(v.z, v.w);
    }
}

// ---------------- HMMA GEMM (fused QKV / O-proj), fp16 2-pass ----------------
// BM=128 BN=128 BK=64; 8 warps (4x2); 2-stage cp.async; 2 CTAs/SM.
#define BK_      64
#define ROWB     144                    // 128B data + 16B pad (conflict-free)
#define MATB     (128*ROWB)             // 18432
#define STGB     (3*MATB)               // 55296 (AH, AL, BH)
#define GSMEM    (2*STGB)               // 110592 (covers 67584B epilogue staging)
#define KTILES   (H_/BK_)               // 64

__device__ __forceinline__ void hmma_load_stage(
    uint32_t sb, int s, const __half* AH, const __half* AL, const __half* BH,
    int M0, int N0, int kt, int tid)
{
    uint32_t base = sb + s*STGB;
    #pragma unroll
    for (int i = 0; i < 12; ++i){
        int c = tid + (i << 8);          // 0..3071
        int mat = c >> 10;               // 0=AH 1=AL 2=BH
        int cc = c & 1023;
        int row = cc >> 3, ch = cc & 7;
        uint32_t soff = (uint32_t)mat*MATB + row*ROWB + (ch << 4);
        const __half* src = (mat == 0) ? AH : (mat == 1) ? AL : BH;
        int base_row = (mat == 2) ? N0 : M0;
        CP_ASYNC16(base + soff, src + (size_t)(base_row + row)*H_ + kt*BK_ + (ch << 3));
    }
}

// mode 0: fused QKV projections (blockIdx.x: 0-31 Q, 32-39 K, 40-47 V)
// mode 1: O projection -> Cout fp32
__global__ __launch_bounds__(256, 2)
void gemm_hmma_kernel(float* __restrict__ Cout, int mode)
{
    extern __shared__ char smem[];
    uint32_t sb = smem_to_u32(smem);
    const int tid = threadIdx.x;
    const int wid = tid >> 5, lane = tid & 31;
    const int wm = wid & 3, wn = wid >> 2;
    const int bx = blockIdx.x;
    const int M0 = blockIdx.y << 7;

    const __half *AH, *AL, *BH;
    int N0, dest, head = 0;
    if (mode == 1){
        AH = g_OH; AL = g_OL; BH = g_Wo;
        N0 = bx << 7; dest = 3;
    } else {
        AH = g_hsH; AL = g_hsL;
        if (bx < 32)      { BH = g_Wq; head = bx;      dest = 0; }
        else if (bx < 40) { BH = g_Wk; head = bx - 32; dest = 1; }
        else              { BH = g_Wv; head = bx - 40; dest = 2; }
        N0 = head << 7;
    }

    float acc[2][8][4];
    #pragma unroll
    for (int m = 0; m < 2; ++m)
        #pragma unroll
        for (int n = 0; n < 8; ++n)
            #pragma unroll
            for (int j = 0; j < 4; ++j) acc[m][n][j] = 0.f;

    hmma_load_stage(sb, 0, AH, AL, BH, M0, N0, 0, tid); CP_COMMIT();

    const uint32_t aRow = (uint32_t)(wm*32 + (lane & 15));
    const uint32_t aColB = (uint32_t)(((lane >> 4) << 3) * 2);
    const uint32_t bRow = (uint32_t)(wn*64 + ((lane & 7) | ((lane & 16) >> 1)));
    const uint32_t bColB = (uint32_t)((((lane >> 3) & 1) << 3) * 2);

    #pragma unroll 1
    for (int kt = 0; kt < KTILES; ++kt){
        const int s = kt & 1;
        CP_WAIT0();
        __syncthreads();
        if (kt + 1 < KTILES){
            hmma_load_stage(sb, s^1, AH, AL, BH, M0, N0, kt + 1, tid);
            CP_COMMIT();
        }

        const uint32_t stA = sb + s*STGB;
        const uint32_t stB = stA + 2*MATB;
        #pragma unroll
        for (int ks = 0; ks < 4; ++ks){
            const uint32_t kB = (uint32_t)(ks << 5);      // 16 fp16 = 32B per k-step
            uint32_t aHr[2][4], aLr[2][4];
            #pragma unroll
            for (int mm = 0; mm < 2; ++mm){
                uint32_t off = (aRow + mm*16)*ROWB + kB + aColB;
                LDSM_X4(aHr[mm], stA + off);
                LDSM_X4(aLr[mm], stA + MATB + off);
            }
            #pragma unroll
            for (int g = 0; g < 4; ++g){
                uint32_t bH[4];
                uint32_t off = (bRow + g*16)*ROWB + kB + bColB;
                LDSM_X4(bH, stB + off);
                MMA_F16(acc[0][2*g],   aHr[0], bH[0], bH[1]);
                MMA_F16(acc[0][2*g+1], aHr[0], bH[2], bH[3]);
                MMA_F16(acc[1][2*g],   aHr[1], bH[0], bH[1]);
                MMA_F16(acc[1][2*g+1], aHr[1], bH[2], bH[3]);
                MMA_F16(acc[0][2*g],   aLr[0], bH[0], bH[1]);
                MMA_F16(acc[0][2*g+1], aLr[0], bH[2], bH[3]);
                MMA_F16(acc[1][2*g],   aLr[1], bH[0], bH[1]);
                MMA_F16(acc[1][2*g+1], aLr[1], bH[2], bH[3]);
            }
        }
    }

    // ---- epilogue ----
    const int rbase = wm*32 + (lane >> 2);
    const int cbase = wn*64 + (lane & 3)*2;
    if (dest == 3 || dest == 2){
        #pragma unroll
        for (int mm = 0; mm < 2; ++mm){
            #pragma unroll
            for (int half = 0; half < 2; ++half){
                int r = M0 + rbase + mm*16 + half*8;
                #pragma unroll
                for (int nn = 0; nn < 8; ++nn){
                    float vx = acc[mm][nn][half*2];
                    float vy = acc[mm][nn][half*2 + 1];
                    if (dest == 3){
                        float2 v; v.x = vx; v.y = vy;
                        *(float2*)(Cout + (size_t)r*H_ + N0 + cbase + nn*8) = v;
                    } else {
                        int bb = r >> 11, ss = r & (S_ - 1);
                        size_t idx = (((size_t)bb*NKV_ + head)*S_ + ss)*HD_ + cbase + nn*8;
                        *(uint32_t*)(g_Vb + idx) = f2h2(vx, vy);
                    }
                }
            }
        }
    } else {
        // Q or K: stage tile in smem, apply RoPE (+scale for Q), write fp16 (paired 4B stores)
        __syncthreads();
        float* sm32 = (float*)smem;
        #pragma unroll
        for (int mm = 0; mm < 2; ++mm){
            #pragma unroll
            for (int half = 0; half < 2; ++half){
                int rl = rbase + mm*16 + half*8;
                #pragma unroll
                for (int nn = 0; nn < 8; ++nn){
                    float2 v;
                    v.x = acc[mm][nn][half*2];
                    v.y = acc[mm][nn][half*2 + 1];
                    *(float2*)(sm32 + rl*132 + cbase + nn*8) = v;
                }
            }
        }
        __syncthreads();
        const float qsc = 0.08838834764831845f;
        #pragma unroll 4
        for (int i = tid; i < 128*32; i += 256){
            int r = i >> 5, jp = (i & 31) << 1;
            int token = M0 + r;
            int bb = token >> 11, ss = token & (S_ - 1);
            float ca = g_cos[(ss << 6) + jp],     sa = g_sin[(ss << 6) + jp];
            float cb = g_cos[(ss << 6) + jp + 1], sb2 = g_sin[(ss << 6) + jp + 1];
            float x1a = sm32[r*132 + jp],      x1b = sm32[r*132 + jp + 1];
            float x2a = sm32[r*132 + jp + 64], x2b = sm32[r*132 + jp + 65];
            float y1a = x1a*ca - x2a*sa,  y1b = x1b*cb - x2b*sb2;
            float y2a = x2a*ca + x1a*sa,  y2b = x2b*cb + x1b*sb2;
            if (dest == 0){
                y1a *= qsc; y1b *= qsc; y2a *= qsc; y2b *= qsc;
                size_t base = (((size_t)bb*NH_ + head)*S_ + ss)*HD_;
                uint32_t h2a, l2a, h2b, l2b;
                split_pair_h(y1a, y1b, h2a, l2a);
                split_pair_h(y2a, y2b, h2b, l2b);
                *(uint32_t*)(g_QbH + base + jp)      = h2a;
                *(uint32_t*)(g_QbH + base + jp + 64) = h2b;
                *(uint32_t*)(g_QbL + base + jp)      = l2a;
                *(uint32_t*)(g_QbL + base + jp + 64) = l2b;
            } else {
                size_t base = (((size_t)bb*NKV_ + head)*S_ + ss)*HD_;
                *(uint32_t*)(g_Kb + base + jp)      = f2h2(y1a, y1b);
                *(uint32_t*)(g_Kb + base + jp + 64) = f2h2(y2a, y2b);
            }
        }
    }
}

// ---------------- HMMA flash attention (fp16 2-pass, 2-stage K/V) -----------
// 256 threads, 8 warps, Q-tile 128 rows, KV-tile 64 keys, 1 CTA/SM.
#define AROWB 272
#define AQMAT (128*AROWB)               // 34816
#define AKMAT (64*AROWB)                // 17408
#define ASTGB (2*AKMAT)                 // K + V = 34816
#define ASMEM (2*AQMAT + 2*ASTGB)       // 139264
#define NKB   (S_/64)                   // 32

__device__ __forceinline__ void attn_load_kv(
    uint32_t st, const __half* Kg, const __half* Vg, int key0, int tid)
{
    #pragma unroll
    for (int i = 0; i < 8; ++i){
        int c = tid + (i << 8);          // 0..2047
        int mat = c >> 10;               // 0=K 1=V
        int cc = c & 1023;
        int row = cc >> 4, ch = cc & 15;
        uint32_t dst = st + (uint32_t)mat*AKMAT + row*AROWB + (ch << 4);
        const __half* src = mat ? Vg : Kg;
        CP_ASYNC16(dst, src + (size_t)(key0 + row)*HD_ + (ch << 3));
    }
}

__global__ __launch_bounds__(256, 1)
void attn_mma_kernel(){
    extern __shared__ char smem[];
    uint32_t sb = smem_to_u32(smem);
    const int tid = threadIdx.x;
    const int wid = tid >> 5, lane = tid & 31;
    const int qb = blockIdx.x, h = blockIdx.y, b = blockIdx.z;
    const int g = h >> 2;

    const __half* QHg = g_QbH + (((size_t)b*NH_ + h)*S_ + (size_t)qb*128)*HD_;
    const __half* QLg = g_QbL + (((size_t)b*NH_ + h)*S_ + (size_t)qb*128)*HD_;
    const __half* Kg  = g_Kb + ((size_t)b*NKV_ + g)*S_*HD_;
    const __half* Vg  = g_Vb + ((size_t)b*NKV_ + g)*S_*HD_;

    const uint32_t QH0 = sb, QL0 = sb + AQMAT;
    const uint32_t KVB = sb + 2*AQMAT;

    #pragma unroll
    for (int i = 0; i < 16; ++i){
        int c = tid + (i << 8);
        int mat = c >> 11;
        int cc = c & 2047;
        int row = cc >> 4, ch = cc & 15;
        uint32_t dst = (mat ? QL0 : QH0) + row*AROWB + (ch << 4);
        const __half* src = mat ? QLg : QHg;
        CP_ASYNC16(dst, src + (size_t)row*HD_ + (ch << 3));
    }
    attn_load_kv(KVB, Kg, Vg, 0, tid);
    CP_COMMIT();

    float m0 = -1e30f, m1 = -1e30f, l0 = 0.f, l1 = 0.f;
    float O[16][4];
    #pragma unroll
    for (int nt = 0; nt < 16; ++nt)
        #pragma unroll
        for (int j = 0; j < 4; ++j) O[nt][j] = 0.f;

    const uint32_t aOff  = (uint32_t)(wid*16 + (lane & 15))*AROWB + ((lane >> 4) << 4);
    const uint32_t bOffK = (uint32_t)((lane & 7) | ((lane & 16) >> 1))*AROWB + (((lane >> 3) & 1) << 4);
    const uint32_t vOff  = (uint32_t)((lane & 7) + (lane & 8))*AROWB + ((lane >> 4) << 4);

    #pragma unroll 1
    for (int kb = 0; kb < NKB; ++kb){
        const int s = kb & 1;
        const uint32_t Kst = KVB + s*ASTGB;
        const uint32_t Vst = Kst + AKMAT;

        CP_WAIT0();
        __syncthreads();
        if (kb + 1 < NKB){
            attn_load_kv(KVB + (s^1)*ASTGB, Kg, Vg, (kb+1)*64, tid);
            CP_COMMIT();
        }

        // ---- S = Q K^T (2-pass fp16) ----
        float Sa[8][4];
        #pragma unroll
        for (int nt = 0; nt < 8; ++nt)
            #pragma unroll
            for (int j = 0; j < 4; ++j) Sa[nt][j] = 0.f;

        #pragma unroll
        for (int ks = 0; ks < 8; ++ks){
            uint32_t aH[4], aL[4];
            LDSM_X4(aH, QH0 + aOff + ks*32);
            LDSM_X4(aL, QL0 + aOff + ks*32);
            #pragma unroll
            for (int gi = 0; gi < 4; ++gi){
                uint32_t bK[4];
                LDSM_X4(bK, Kst + bOffK + gi*(16*AROWB) + ks*32);
                MMA_F16(Sa[2*gi],   aH, bK[0], bK[1]);
                MMA_F16(Sa[2*gi+1], aH, bK[2], bK[3]);
                MMA_F16(Sa[2*gi],   aL, bK[0], bK[1]);
                MMA_F16(Sa[2*gi+1], aL, bK[2], bK[3]);
            }
        }

        // ---- online softmax ----
        float mb0 = -1e30f, mb1 = -1e30f;
        #pragma unroll
        for (int nt = 0; nt < 8; ++nt){
            mb0 = fmaxf(mb0, fmaxf(Sa[nt][0], Sa[nt][1]));
            mb1 = fmaxf(mb1, fmaxf(Sa[nt][2], Sa[nt][3]));
        }
        mb0 = fmaxf(mb0, __shfl_xor_sync(0xffffffffu, mb0, 1));
        mb0 = fmaxf(mb0, __shfl_xor_sync(0xffffffffu, mb0, 2));
        mb1 = fmaxf(mb1, __shfl_xor_sync(0xffffffffu, mb1, 1));
        mb1 = fmaxf(mb1, __shfl_xor_sync(0xffffffffu, mb1, 2));
        float m0n = fmaxf(m0, mb0), m1n = fmaxf(m1, mb1);
        float corr0 = fast_exp(m0 - m0n), corr1 = fast_exp(m1 - m1n);
        m0 = m0n; m1 = m1n;

        float ls0 = 0.f, ls1 = 0.f;
        #pragma unroll
        for (int nt = 0; nt < 8; ++nt){
            Sa[nt][0] = fast_exp(Sa[nt][0] - m0);
            Sa[nt][1] = fast_exp(Sa[nt][1] - m0);
            Sa[nt][2] = fast_exp(Sa[nt][2] - m1);
            Sa[nt][3] = fast_exp(Sa[nt][3] - m1);
            ls0 += Sa[nt][0] + Sa[nt][1];
            ls1 += Sa[nt][2] + Sa[nt][3];
        }
        ls0 += __shfl_xor_sync(0xffffffffu, ls0, 1);
        ls0 += __shfl_xor_sync(0xffffffffu, ls0, 2);
        ls1 += __shfl_xor_sync(0xffffffffu, ls1, 1);
        ls1 += __shfl_xor_sync(0xffffffffu, ls1, 2);
        l0 = l0*corr0 + ls0;
        l1 = l1*corr1 + ls1;

        // skip the rescale when corr == 1 exactly (bit-identical: x*1 == x)
        if (!__all_sync(0xffffffffu, (corr0 == 1.0f) && (corr1 == 1.0f))){
            #pragma unroll
            for (int nt = 0; nt < 16; ++nt){
                O[nt][0] *= corr0; O[nt][1] *= corr0;
                O[nt][2] *= corr1; O[nt][3] *= corr1;
            }
        }

        // ---- P -> A fragments (fp16 hi/lo) ----
        uint32_t aPh[4][4], aPl[4][4];
        #pragma unroll
        for (int kt = 0; kt < 4; ++kt){
            split_pair_h(Sa[2*kt][0],   Sa[2*kt][1],   aPh[kt][0], aPl[kt][0]);
            split_pair_h(Sa[2*kt][2],   Sa[2*kt][3],   aPh[kt][1], aPl[kt][1]);
            split_pair_h(Sa[2*kt+1][0], Sa[2*kt+1][1], aPh[kt][2], aPl[kt][2]);
            split_pair_h(Sa[2*kt+1][2], Sa[2*kt+1][3], aPh[kt][3], aPl[kt][3]);
        }

        // ---- O += P V (2-pass fp16, V via ldmatrix.trans) ----
        #pragma unroll
        for (int kt = 0; kt < 4; ++kt){
            #pragma unroll
            for (int dp = 0; dp < 8; ++dp){
                uint32_t bV[4];
                LDSM_X4_T(bV, Vst + vOff + kt*(16*AROWB) + dp*32);
                MMA_F16(O[2*dp],   aPh[kt], bV[0], bV[1]);
                MMA_F16(O[2*dp+1], aPh[kt], bV[2], bV[3]);
                MMA_F16(O[2*dp],   aPl[kt], bV[0], bV[1]);
                MMA_F16(O[2*dp+1], aPl[kt], bV[2], bV[3]);
            }
        }
    }

    // ---- epilogue: normalize, fp16 hi/lo to g_OH/g_OL ----
    const float inv0 = 1.0f / l0, inv1 = 1.0f / l1;
    const int s0 = qb*128 + wid*16 + (lane >> 2);
    const size_t ob = (size_t)b*S_*H_ + (size_t)h*HD_;
    #pragma unroll
    for (int nt = 0; nt < 16; ++nt){
        int d = nt*8 + (lane & 3)*2;
        uint32_t h2, l2;
        split_pair_h(O[nt][0]*inv0, O[nt][1]*inv0, h2, l2);
        size_t idx0 = ob + (size_t)s0*H_ + d;
        *(uint32_t*)(g_OH + idx0) = h2;
        *(uint32_t*)(g_OL + idx0) = l2;
        split_pair_h(O[nt][2]*inv1, O[nt][3]*inv1, h2, l2);
        size_t idx1 = ob + (size_t)(s0 + 8)*H_ + d;
        *(uint32_t*)(g_OH + idx1) = h2;
        *(uint32_t*)(g_OL + idx1) = l2;
    }
}

// ---------------- launch ----------------------------------------------------
extern "C" void kernel_launch(void* const* d_in, const int* in_sizes, int n_in,
                              void* d_out, int out_size)
{
    const float* hs = (const float*)d_in[0];
    const float* Wq = (const float*)d_in[1];
    const float* Wk = (const float*)d_in[2];
    const float* Wv = (const float*)d_in[3];
    const float* Wo = (const float*)d_in[4];
    float* out = (float*)d_out;

    rope_tables_kernel<<<(S_*64 + 255)/256, 256>>>();
    split_hs_kernel<<<TOK*H_/(8*256), 256>>>(hs);
    convert_weights_kernel<<<(QWN + 2*KWN + H_*H_)/(8*256), 256>>>(Wq, Wk, Wv, Wo);

    cudaFuncSetAttribute(gemm_hmma_kernel, cudaFuncAttributeMaxDynamicSharedMemorySize, GSMEM);
    cudaFuncSetAttribute(attn_mma_kernel, cudaFuncAttributeMaxDynamicSharedMemorySize, ASMEM);

    // fused Q/K/V projections with RoPE + fp16 conversion in epilogue
    gemm_hmma_kernel<<<dim3(48, 32), 256, GSMEM>>>(nullptr, 0);

    // flash attention (128-row Q tiles)
    attn_mma_kernel<<<dim3(S_/128, NH_, B_), 256, ASMEM>>>();

    // output projection -> d_out
    gemm_hmma_kernel<<<dim3(32, 32), 256, GSMEM>>>(out, 1);
}

// round 12
// speedup vs baseline: 1.1336x; 1.0059x over previous
#include <cuda_runtime.h>
#include <cuda_fp16.h>
#include <math.h>
#include <stdint.h>

#define B_   2
#define S_   2048
#define H_   4096
#define NH_  32
#define NKV_ 8
#define HD_  128
#define TOK  (B_*S_)        // 4096
#define QWN  (NH_*HD_*H_)   // 16777216
#define KWN  (NKV_*HD_*H_)  // 4194304

// ---------------- scratch (static device globals; no allocation) ----------
__device__ float g_cos[S_*64];
__device__ float g_sin[S_*64];

// fp16 operands
__device__ __half g_hsH[(size_t)TOK*H_], g_hsL[(size_t)TOK*H_];
__device__ __half g_Wq[(size_t)QWN];
__device__ __half g_Wk[(size_t)KWN];
__device__ __half g_Wv[(size_t)KWN];
__device__ __half g_Wo[(size_t)H_*H_];
__device__ __half g_OH[(size_t)TOK*H_], g_OL[(size_t)TOK*H_];

// attention operands (fp16; RoPE and scale pre-applied)
__device__ __half g_QbH[(size_t)B_*NH_*S_*HD_], g_QbL[(size_t)B_*NH_*S_*HD_];
__device__ __half g_Kb[(size_t)B_*NKV_*S_*HD_];
__device__ __half g_Vb[(size_t)B_*NKV_*S_*HD_];

// ---------------- helpers ----------------------------------------------------
__device__ __forceinline__ uint32_t smem_to_u32(const void* p){
    uint32_t a;
    asm("{ .reg .u64 t; cvta.to.shared.u64 t, %1; cvt.u32.u64 %0, t; }" : "=r"(a) : "l"(p));
    return a;
}
#define CP_ASYNC16(dst, src) \
    asm volatile("cp.async.cg.shared.global [%0], [%1], 16;" :: "r"(dst), "l"(src))
#define CP_COMMIT() asm volatile("cp.async.commit_group;" ::: "memory")
#define CP_WAIT0()  asm volatile("cp.async.wait_group 0;" ::: "memory")

#define LDSM_X4(r, addr) \
    asm volatile("ldmatrix.sync.aligned.m8n8.x4.shared.b16 {%0,%1,%2,%3}, [%4];" \
        : "=r"((r)[0]),"=r"((r)[1]),"=r"((r)[2]),"=r"((r)[3]) : "r"(addr))
#define LDSM_X4_T(r, addr) \
    asm volatile("ldmatrix.sync.aligned.m8n8.x4.trans.shared.b16 {%0,%1,%2,%3}, [%4];" \
        : "=r"((r)[0]),"=r"((r)[1]),"=r"((r)[2]),"=r"((r)[3]) : "r"(addr))

#define MMA_F16(c, a, b0, b1) \
    asm volatile("mma.sync.aligned.m16n8k16.row.col.f32.f16.f16.f32 " \
        "{%0,%1,%2,%3},{%4,%5,%6,%7},{%8,%9},{%0,%1,%2,%3};" \
        : "+f"((c)[0]),"+f"((c)[1]),"+f"((c)[2]),"+f"((c)[3]) \
        : "r"((a)[0]),"r"((a)[1]),"r"((a)[2]),"r"((a)[3]), "r"(b0),"r"(b1))

__device__ __forceinline__ uint32_t f2h2(float x, float y){
    __half2 h = __floats2half2_rn(x, y);
    return *(uint32_t*)&h;
}
__device__ __forceinline__ void split_pair_h(float x, float y, uint32_t& h2, uint32_t& l2){
    h2 = f2h2(x, y);
    float2 f = __half22float2(*(__half2*)&h2);
    l2 = f2h2(x - f.x, y - f.y);
}
// fast e^x on FMA/ALU pipes. valid for x <= 0, clamps below -87. fast_exp(0)==1.0f exactly.
__device__ __forceinline__ float fast_exp(float x){
    x = fmaxf(x, -87.0f);
    float y = x * 1.4426950408889634f;
    float r = __fadd_rn(y, 12582912.0f);
    float f = y - __fadd_rn(r, -12582912.0f);
    float p = 1.5403530e-4f;
    p = __fmaf_rn(p, f, 1.3333558e-3f);
    p = __fmaf_rn(p, f, 9.6181291e-3f);
    p = __fmaf_rn(p, f, 5.5504109e-2f);
    p = __fmaf_rn(p, f, 2.4022651e-1f);
    p = __fmaf_rn(p, f, 6.9314718e-1f);
    p = __fmaf_rn(p, f, 1.0f);
    int n = __float_as_int(r) - 0x4B400000;
    return __int_as_float(__float_as_int(p) + (n << 23));
}

// ---------------- rope tables ----------------------------------------------
__global__ void rope_tables_kernel(){
    int idx = blockIdx.x * blockDim.x + threadIdx.x;
    if (idx >= S_*64) return;
    int s = idx >> 6, j = idx & 63;
    double inv = pow(500000.0, -((double)j)/64.0);
    float ang = (float)s * (float)inv;
    g_cos[idx] = (float)cos((double)ang);
    g_sin[idx] = (float)sin((double)ang);
}

// ---------------- fp32 -> fp16 hi/lo split (hidden states), 8 floats/thread --
__global__ void split_hs_kernel(const float* __restrict__ src){
    size_t i = (((size_t)blockIdx.x << 8) + threadIdx.x) << 3;
    #pragma unroll
    for (int u = 0; u < 2; ++u){
        float4 v = *(const float4*)(src + i + u*4);
        uint32_t h0, l0, h1, l1;
        split_pair_h(v.x, v.y, h0, l0);
        split_pair_h(v.z, v.w, h1, l1);
        *(uint32_t*)(g_hsH + i + u*4)     = h0;
        *(uint32_t*)(g_hsH + i + u*4 + 2) = h1;
        *(uint32_t*)(g_hsL + i + u*4)     = l0;
        *(uint32_t*)(g_hsL + i + u*4 + 2) = l1;
    }
}

// ---------------- all weights fp32 -> fp16, one kernel, 8 floats/thread -----
__global__ void convert_weights_kernel(const float* __restrict__ Wq, const float* __restrict__ Wk,
                                       const float* __restrict__ Wv, const float* __restrict__ Wo){
    size_t i = (((size_t)blockIdx.x << 8) + threadIdx.x) << 3;
    const float* src; __half* dst; size_t off;
    if (i < QWN)              { src = Wq; dst = g_Wq; off = i; }
    else if (i < QWN + KWN)   { src = Wk; dst = g_Wk; off = i - QWN; }
    else if (i < QWN + 2*KWN) { src = Wv; dst = g_Wv; off = i - QWN - KWN; }
    else                      { src = Wo; dst = g_Wo; off = i - QWN - 2*KWN; }
    #pragma unroll
    for (int u = 0; u < 2; ++u){
        float4 v = *(const float4*)(src + off + u*4);
        *(uint32_t*)(dst + off + u*4)     = f2h2(v.x, v.y);
        *(uint32_t*)(dst + off + u*4 + 2) = f2h2(v.z, v.w);
    }
}

// ---------------- HMMA GEMM (fused QKV / O-proj), fp16 2-pass ----------------
// BM=128 BN=128 BK=64; 8 warps (4x2); 2-stage cp.async; 2 CTAs/SM.
#define BK_      64
#define ROWB     144                    // 128B data + 16B pad (conflict-free)
#define MATB     (128*ROWB)             // 18432
#define STGB     (3*MATB)               // 55296 (AH, AL, BH)
#define GSMEM    (2*STGB)               // 110592 (covers 67584B epilogue staging)
#define KTILES   (H_/BK_)               // 64

__device__ __forceinline__ void hmma_load_stage(
    uint32_t sb, int s, const __half* AH, const __half* AL, const __half* BH,
    int M0, int N0, int kt, int tid)
{
    uint32_t base = sb + s*STGB;
    #pragma unroll
    for (int i = 0; i < 12; ++i){
        int c = tid + (i << 8);          // 0..3071
        int mat = c >> 10;               // 0=AH 1=AL 2=BH
        int cc = c & 1023;
        int row = cc >> 3, ch = cc & 7;
        uint32_t soff = (uint32_t)mat*MATB + row*ROWB + (ch << 4);
        const __half* src = (mat == 0) ? AH : (mat == 1) ? AL : BH;
        int base_row = (mat == 2) ? N0 : M0;
        CP_ASYNC16(base + soff, src + (size_t)(base_row + row)*H_ + kt*BK_ + (ch << 3));
    }
}

// mode 0: fused QKV projections (blockIdx.x: 0-31 Q, 32-39 K, 40-47 V)
// mode 1: O projection -> Cout fp32
__global__ __launch_bounds__(256, 2)
void gemm_hmma_kernel(float* __restrict__ Cout, int mode)
{
    extern __shared__ char smem[];
    uint32_t sb = smem_to_u32(smem);
    const int tid = threadIdx.x;
    const int wid = tid >> 5, lane = tid & 31;
    const int wm = wid & 3, wn = wid >> 2;
    const int bx = blockIdx.x;
    const int M0 = blockIdx.y << 7;

    const __half *AH, *AL, *BH;
    int N0, dest, head = 0;
    if (mode == 1){
        AH = g_OH; AL = g_OL; BH = g_Wo;
        N0 = bx << 7; dest = 3;
    } else {
        AH = g_hsH; AL = g_hsL;
        if (bx < 32)      { BH = g_Wq; head = bx;      dest = 0; }
        else if (bx < 40) { BH = g_Wk; head = bx - 32; dest = 1; }
        else              { BH = g_Wv; head = bx - 40; dest = 2; }
        N0 = head << 7;
    }

    float acc[2][8][4];
    #pragma unroll
    for (int m = 0; m < 2; ++m)
        #pragma unroll
        for (int n = 0; n < 8; ++n)
            #pragma unroll
            for (int j = 0; j < 4; ++j) acc[m][n][j] = 0.f;

    hmma_load_stage(sb, 0, AH, AL, BH, M0, N0, 0, tid); CP_COMMIT();

    const uint32_t aRow = (uint32_t)(wm*32 + (lane & 15));
    const uint32_t aColB = (uint32_t)(((lane >> 4) << 3) * 2);
    const uint32_t bRow = (uint32_t)(wn*64 + ((lane & 7) | ((lane & 16) >> 1)));
    const uint32_t bColB = (uint32_t)((((lane >> 3) & 1) << 3) * 2);

    #pragma unroll 1
    for (int kt = 0; kt < KTILES; ++kt){
        const int s = kt & 1;
        CP_WAIT0();
        __syncthreads();
        if (kt + 1 < KTILES){
            hmma_load_stage(sb, s^1, AH, AL, BH, M0, N0, kt + 1, tid);
            CP_COMMIT();
        }

        const uint32_t stA = sb + s*STGB;
        const uint32_t stB = stA + 2*MATB;
        #pragma unroll
        for (int ks = 0; ks < 4; ++ks){
            const uint32_t kB = (uint32_t)(ks << 5);      // 16 fp16 = 32B per k-step
            uint32_t aHr[2][4], aLr[2][4];
            #pragma unroll
            for (int mm = 0; mm < 2; ++mm){
                uint32_t off = (aRow + mm*16)*ROWB + kB + aColB;
                LDSM_X4(aHr[mm], stA + off);
                LDSM_X4(aLr[mm], stA + MATB + off);
            }
            #pragma unroll
            for (int g = 0; g < 4; ++g){
                uint32_t bH[4];
                uint32_t off = (bRow + g*16)*ROWB + kB + bColB;
                LDSM_X4(bH, stB + off);
                MMA_F16(acc[0][2*g],   aHr[0], bH[0], bH[1]);
                MMA_F16(acc[0][2*g+1], aHr[0], bH[2], bH[3]);
                MMA_F16(acc[1][2*g],   aHr[1], bH[0], bH[1]);
                MMA_F16(acc[1][2*g+1], aHr[1], bH[2], bH[3]);
                MMA_F16(acc[0][2*g],   aLr[0], bH[0], bH[1]);
                MMA_F16(acc[0][2*g+1], aLr[0], bH[2], bH[3]);
                MMA_F16(acc[1][2*g],   aLr[1], bH[0], bH[1]);
                MMA_F16(acc[1][2*g+1], aLr[1], bH[2], bH[3]);
            }
        }
    }

    // ---- epilogue ----
    const int rbase = wm*32 + (lane >> 2);
    const int cbase = wn*64 + (lane & 3)*2;
    if (dest == 3 || dest == 2){
        #pragma unroll
        for (int mm = 0; mm < 2; ++mm){
            #pragma unroll
            for (int half = 0; half < 2; ++half){
                int r = M0 + rbase + mm*16 + half*8;
                #pragma unroll
                for (int nn = 0; nn < 8; ++nn){
                    float vx = acc[mm][nn][half*2];
                    float vy = acc[mm][nn][half*2 + 1];
                    if (dest == 3){
                        float2 v; v.x = vx; v.y = vy;
                        *(float2*)(Cout + (size_t)r*H_ + N0 + cbase + nn*8) = v;
                    } else {
                        int bb = r >> 11, ss = r & (S_ - 1);
                        size_t idx = (((size_t)bb*NKV_ + head)*S_ + ss)*HD_ + cbase + nn*8;
                        *(uint32_t*)(g_Vb + idx) = f2h2(vx, vy);
                    }
                }
            }
        }
    } else {
        // Q or K: stage tile in smem, apply RoPE (+scale for Q), write fp16 (paired 4B stores)
        __syncthreads();
        float* sm32 = (float*)smem;
        #pragma unroll
        for (int mm = 0; mm < 2; ++mm){
            #pragma unroll
            for (int half = 0; half < 2; ++half){
                int rl = rbase + mm*16 + half*8;
                #pragma unroll
                for (int nn = 0; nn < 8; ++nn){
                    float2 v;
                    v.x = acc[mm][nn][half*2];
                    v.y = acc[mm][nn][half*2 + 1];
                    *(float2*)(sm32 + rl*132 + cbase + nn*8) = v;
                }
            }
        }
        __syncthreads();
        const float qsc = 0.08838834764831845f;
        #pragma unroll 4
        for (int i = tid; i < 128*32; i += 256){
            int r = i >> 5, jp = (i & 31) << 1;
            int token = M0 + r;
            int bb = token >> 11, ss = token & (S_ - 1);
            float ca = g_cos[(ss << 6) + jp],     sa = g_sin[(ss << 6) + jp];
            float cb = g_cos[(ss << 6) + jp + 1], sb2 = g_sin[(ss << 6) + jp + 1];
            float x1a = sm32[r*132 + jp],      x1b = sm32[r*132 + jp + 1];
            float x2a = sm32[r*132 + jp + 64], x2b = sm32[r*132 + jp + 65];
            float y1a = x1a*ca - x2a*sa,  y1b = x1b*cb - x2b*sb2;
            float y2a = x2a*ca + x1a*sa,  y2b = x2b*cb + x1b*sb2;
            if (dest == 0){
                y1a *= qsc; y1b *= qsc; y2a *= qsc; y2b *= qsc;
                size_t base = (((size_t)bb*NH_ + head)*S_ + ss)*HD_;
                uint32_t h2a, l2a, h2b, l2b;
                split_pair_h(y1a, y1b, h2a, l2a);
                split_pair_h(y2a, y2b, h2b, l2b);
                *(uint32_t*)(g_QbH + base + jp)      = h2a;
                *(uint32_t*)(g_QbH + base + jp + 64) = h2b;
                *(uint32_t*)(g_QbL + base + jp)      = l2a;
                *(uint32_t*)(g_QbL + base + jp + 64) = l2b;
            } else {
                size_t base = (((size_t)bb*NKV_ + head)*S_ + ss)*HD_;
                *(uint32_t*)(g_Kb + base + jp)      = f2h2(y1a, y1b);
                *(uint32_t*)(g_Kb + base + jp + 64) = f2h2(y2a, y2b);
            }
        }
    }
}

// ---------------- HMMA flash attention (fp16 2-pass, 2-stage 32-key KV) -----
// 256 threads, 8 warps, Q-tile 128 rows, KV-tile 32 keys, 2 CTAs/SM.
#define AROWB 272
#define AQMAT (128*AROWB)               // 34816
#define AKMAT (32*AROWB)                // 8704
#define ASTGB (2*AKMAT)                 // K + V = 17408
#define ASMEM (2*AQMAT + 2*ASTGB)       // 104448 -> 2 CTAs/SM
#define NKB   (S_/32)                   // 64

__device__ __forceinline__ void attn_load_kv(
    uint32_t st, const __half* Kg, const __half* Vg, int key0, int tid)
{
    #pragma unroll
    for (int i = 0; i < 4; ++i){
        int c = tid + (i << 8);          // 0..1023
        int mat = c >> 9;                // 0=K 1=V (512 chunks each)
        int cc = c & 511;
        int row = cc >> 4, ch = cc & 15;
        uint32_t dst = st + (uint32_t)mat*AKMAT + row*AROWB + (ch << 4);
        const __half* src = mat ? Vg : Kg;
        CP_ASYNC16(dst, src + (size_t)(key0 + row)*HD_ + (ch << 3));
    }
}

__global__ __launch_bounds__(256, 2)
void attn_mma_kernel(){
    extern __shared__ char smem[];
    uint32_t sb = smem_to_u32(smem);
    const int tid = threadIdx.x;
    const int wid = tid >> 5, lane = tid & 31;
    const int qb = blockIdx.x, h = blockIdx.y, b = blockIdx.z;
    const int g = h >> 2;

    const __half* QHg = g_QbH + (((size_t)b*NH_ + h)*S_ + (size_t)qb*128)*HD_;
    const __half* QLg = g_QbL + (((size_t)b*NH_ + h)*S_ + (size_t)qb*128)*HD_;
    const __half* Kg  = g_Kb + ((size_t)b*NKV_ + g)*S_*HD_;
    const __half* Vg  = g_Vb + ((size_t)b*NKV_ + g)*S_*HD_;

    const uint32_t QH0 = sb, QL0 = sb + AQMAT;
    const uint32_t KVB = sb + 2*AQMAT;

    #pragma unroll
    for (int i = 0; i < 16; ++i){
        int c = tid + (i << 8);
        int mat = c >> 11;
        int cc = c & 2047;
        int row = cc >> 4, ch = cc & 15;
        uint32_t dst = (mat ? QL0 : QH0) + row*AROWB + (ch << 4);
        const __half* src = mat ? QLg : QHg;
        CP_ASYNC16(dst, src + (size_t)row*HD_ + (ch << 3));
    }
    attn_load_kv(KVB, Kg, Vg, 0, tid);
    CP_COMMIT();

    float m0 = -1e30f, m1 = -1e30f, l0 = 0.f, l1 = 0.f;
    float O[16][4];
    #pragma unroll
    for (int nt = 0; nt < 16; ++nt)
        #pragma unroll
        for (int j = 0; j < 4; ++j) O[nt][j] = 0.f;

    const uint32_t aOff  = (uint32_t)(wid*16 + (lane & 15))*AROWB + ((lane >> 4) << 4);
    const uint32_t bOffK = (uint32_t)((lane & 7) | ((lane & 16) >> 1))*AROWB + (((lane >> 3) & 1) << 4);
    const uint32_t vOff  = (uint32_t)((lane & 7) + (lane & 8))*AROWB + ((lane >> 4) << 4);

    #pragma unroll 1
    for (int kb = 0; kb < NKB; ++kb){
        const int s = kb & 1;
        const uint32_t Kst = KVB + s*ASTGB;
        const uint32_t Vst = Kst + AKMAT;

        CP_WAIT0();
        __syncthreads();
        if (kb + 1 < NKB){
            attn_load_kv(KVB + (s^1)*ASTGB, Kg, Vg, (kb+1)*32, tid);
            CP_COMMIT();
        }

        // ---- S = Q K^T (2-pass fp16), 32 keys ----
        float Sa[4][4];
        #pragma unroll
        for (int nt = 0; nt < 4; ++nt)
            #pragma unroll
            for (int j = 0; j < 4; ++j) Sa[nt][j] = 0.f;

        #pragma unroll
        for (int ks = 0; ks < 8; ++ks){
            uint32_t aH[4], aL[4];
            LDSM_X4(aH, QH0 + aOff + ks*32);
            LDSM_X4(aL, QL0 + aOff + ks*32);
            #pragma unroll
            for (int gi = 0; gi < 2; ++gi){
                uint32_t bK[4];
                LDSM_X4(bK, Kst + bOffK + gi*(16*AROWB) + ks*32);
                MMA_F16(Sa[2*gi],   aH, bK[0], bK[1]);
                MMA_F16(Sa[2*gi+1], aH, bK[2], bK[3]);
                MMA_F16(Sa[2*gi],   aL, bK[0], bK[1]);
                MMA_F16(Sa[2*gi+1], aL, bK[2], bK[3]);
            }
        }

        // ---- online softmax ----
        float mb0 = -1e30f, mb1 = -1e30f;
        #pragma unroll
        for (int nt = 0; nt < 4; ++nt){
            mb0 = fmaxf(mb0, fmaxf(Sa[nt][0], Sa[nt][1]));
            mb1 = fmaxf(mb1, fmaxf(Sa[nt][2], Sa[nt][3]));
        }
        mb0 = fmaxf(mb0, __shfl_xor_sync(0xffffffffu, mb0, 1));
        mb0 = fmaxf(mb0, __shfl_xor_sync(0xffffffffu, mb0, 2));
        mb1 = fmaxf(mb1, __shfl_xor_sync(0xffffffffu, mb1, 1));
        mb1 = fmaxf(mb1, __shfl_xor_sync(0xffffffffu, mb1, 2));
        float m0n = fmaxf(m0, mb0), m1n = fmaxf(m1, mb1);
        float corr0 = fast_exp(m0 - m0n), corr1 = fast_exp(m1 - m1n);
        m0 = m0n; m1 = m1n;

        float ls0 = 0.f, ls1 = 0.f;
        #pragma unroll
        for (int nt = 0; nt < 4; ++nt){
            Sa[nt][0] = fast_exp(Sa[nt][0] - m0);
            Sa[nt][1] = fast_exp(Sa[nt][1] - m0);
            Sa[nt][2] = fast_exp(Sa[nt][2] - m1);
            Sa[nt][3] = fast_exp(Sa[nt][3] - m1);
            ls0 += Sa[nt][0] + Sa[nt][1];
            ls1 += Sa[nt][2] + Sa[nt][3];
        }
        ls0 += __shfl_xor_sync(0xffffffffu, ls0, 1);
        ls0 += __shfl_xor_sync(0xffffffffu, ls0, 2);
        ls1 += __shfl_xor_sync(0xffffffffu, ls1, 1);
        ls1 += __shfl_xor_sync(0xffffffffu, ls1, 2);
        l0 = l0*corr0 + ls0;
        l1 = l1*corr1 + ls1;

        // skip the rescale when corr == 1 exactly (bit-identical: x*1 == x)
        if (!__all_sync(0xffffffffu, (corr0 == 1.0f) && (corr1 == 1.0f))){
            #pragma unroll
            for (int nt = 0; nt < 16; ++nt){
                O[nt][0] *= corr0; O[nt][1] *= corr0;
                O[nt][2] *= corr1; O[nt][3] *= corr1;
            }
        }

        // ---- P -> A fragments (fp16 hi/lo) ----
        uint32_t aPh[2][4], aPl[2][4];
        #pragma unroll
        for (int kt = 0; kt < 2; ++kt){
            split_pair_h(Sa[2*kt][0],   Sa[2*kt][1],   aPh[kt][0], aPl[kt][0]);
            split_pair_h(Sa[2*kt][2],   Sa[2*kt][3],   aPh[kt][1], aPl[kt][1]);
            split_pair_h(Sa[2*kt+1][0], Sa[2*kt+1][1], aPh[kt][2], aPl[kt][2]);
            split_pair_h(Sa[2*kt+1][2], Sa[2*kt+1][3], aPh[kt][3], aPl[kt][3]);
        }

        // ---- O += P V (2-pass fp16, V via ldmatrix.trans) ----
        #pragma unroll
        for (int kt = 0; kt < 2; ++kt){
            #pragma unroll
            for (int dp = 0; dp < 8; ++dp){
                uint32_t bV[4];
                LDSM_X4_T(bV, Vst + vOff + kt*(16*AROWB) + dp*32);
                MMA_F16(O[2*dp],   aPh[kt], bV[0], bV[1]);
                MMA_F16(O[2*dp+1], aPh[kt], bV[2], bV[3]);
                MMA_F16(O[2*dp],   aPl[kt], bV[0], bV[1]);
                MMA_F16(O[2*dp+1], aPl[kt], bV[2], bV[3]);
            }
        }
    }

    // ---- epilogue: normalize, fp16 hi/lo to g_OH/g_OL ----
    const float inv0 = 1.0f / l0, inv1 = 1.0f / l1;
    const int s0 = qb*128 + wid*16 + (lane >> 2);
    const size_t ob = (size_t)b*S_*H_ + (size_t)h*HD_;
    #pragma unroll
    for (int nt = 0; nt < 16; ++nt){
        int d = nt*8 + (lane & 3)*2;
        uint32_t h2, l2;
        split_pair_h(O[nt][0]*inv0, O[nt][1]*inv0, h2, l2);
        size_t idx0 = ob + (size_t)s0*H_ + d;
        *(uint32_t*)(g_OH + idx0) = h2;
        *(uint32_t*)(g_OL + idx0) = l2;
        split_pair_h(O[nt][2]*inv1, O[nt][3]*inv1, h2, l2);
        size_t idx1 = ob + (size_t)(s0 + 8)*H_ + d;
        *(uint32_t*)(g_OH + idx1) = h2;
        *(uint32_t*)(g_OL + idx1) = l2;
    }
}

// ---------------- launch ----------------------------------------------------
extern "C" void kernel_launch(void* const* d_in, const int* in_sizes, int n_in,
                              void* d_out, int out_size)
{
    const float* hs = (const float*)d_in[0];
    const float* Wq = (const float*)d_in[1];
    const float* Wk = (const float*)d_in[2];
    const float* Wv = (const float*)d_in[3];
    const float* Wo = (const float*)d_in[4];
    float* out = (float*)d_out;

    rope_tables_kernel<<<(S_*64 + 255)/256, 256>>>();
    split_hs_kernel<<<TOK*H_/(8*256), 256>>>(hs);
    convert_weights_kernel<<<(QWN + 2*KWN + H_*H_)/(8*256), 256>>>(Wq, Wk, Wv, Wo);

    cudaFuncSetAttribute(gemm_hmma_kernel, cudaFuncAttributeMaxDynamicSharedMemorySize, GSMEM);
    cudaFuncSetAttribute(attn_mma_kernel, cudaFuncAttributeMaxDynamicSharedMemorySize, ASMEM);

    // fused Q/K/V projections with RoPE + fp16 conversion in epilogue
    gemm_hmma_kernel<<<dim3(48, 32), 256, GSMEM>>>(nullptr, 0);

    // flash attention (128-row Q tiles, 32-key KV tiles, 2 CTAs/SM)
    attn_mma_kernel<<<dim3(S_/128, NH_, B_), 256, ASMEM>>>();

    // output projection -> d_out
    gemm_hmma_kernel<<<dim3(32, 32), 256, GSMEM>>>(out, 1);
}

// round 13
// speedup vs baseline: 1.1445x; 1.0096x over previous
#include <cuda_runtime.h>
#include <cuda_fp16.h>
#include <math.h>
#include <stdint.h>

#define B_   2
#define S_   2048
#define H_   4096
#define NH_  32
#define NKV_ 8
#define HD_  128
#define TOK  (B_*S_)        // 4096
#define QWN  (NH_*HD_*H_)   // 16777216
#define KWN  (NKV_*HD_*H_)  // 4194304

// ---------------- scratch (static device globals; no allocation) ----------
__device__ float g_cos[S_*64];
__device__ float g_sin[S_*64];

// fp16 operands
__device__ __half g_hsH[(size_t)TOK*H_], g_hsL[(size_t)TOK*H_];
__device__ __half g_Wq[(size_t)QWN];
__device__ __half g_Wk[(size_t)KWN];
__device__ __half g_Wv[(size_t)KWN];
__device__ __half g_Wo[(size_t)H_*H_];
__device__ __half g_OH[(size_t)TOK*H_], g_OL[(size_t)TOK*H_];

// attention operands (fp16; RoPE and scale pre-applied)
__device__ __half g_QbH[(size_t)B_*NH_*S_*HD_], g_QbL[(size_t)B_*NH_*S_*HD_];
__device__ __half g_Kb[(size_t)B_*NKV_*S_*HD_];
__device__ __half g_Vb[(size_t)B_*NKV_*S_*HD_];

// ---------------- helpers ----------------------------------------------------
__device__ __forceinline__ uint32_t smem_to_u32(const void* p){
    uint32_t a;
    asm("{ .reg .u64 t; cvta.to.shared.u64 t, %1; cvt.u32.u64 %0, t; }" : "=r"(a) : "l"(p));
    return a;
}
#define CP_ASYNC16(dst, src) \
    asm volatile("cp.async.cg.shared.global [%0], [%1], 16;" :: "r"(dst), "l"(src))
#define CP_COMMIT() asm volatile("cp.async.commit_group;" ::: "memory")
#define CP_WAIT0()  asm volatile("cp.async.wait_group 0;" ::: "memory")

#define LDSM_X4(r, addr) \
    asm volatile("ldmatrix.sync.aligned.m8n8.x4.shared.b16 {%0,%1,%2,%3}, [%4];" \
        : "=r"((r)[0]),"=r"((r)[1]),"=r"((r)[2]),"=r"((r)[3]) : "r"(addr))
#define LDSM_X4_T(r, addr) \
    asm volatile("ldmatrix.sync.aligned.m8n8.x4.trans.shared.b16 {%0,%1,%2,%3}, [%4];" \
        : "=r"((r)[0]),"=r"((r)[1]),"=r"((r)[2]),"=r"((r)[3]) : "r"(addr))

#define MMA_F16(c, a, b0, b1) \
    asm volatile("mma.sync.aligned.m16n8k16.row.col.f32.f16.f16.f32 " \
        "{%0,%1,%2,%3},{%4,%5,%6,%7},{%8,%9},{%0,%1,%2,%3};" \
        : "+f"((c)[0]),"+f"((c)[1]),"+f"((c)[2]),"+f"((c)[3]) \
        : "r"((a)[0]),"r"((a)[1]),"r"((a)[2]),"r"((a)[3]), "r"(b0),"r"(b1))

// f16-accumulator HMMA: D = {d0,d1} packed half2 (c0,c1) and (c2,c3)
#define MMA_F16ACC(d, a, b0, b1) \
    asm volatile("mma.sync.aligned.m16n8k16.row.col.f16.f16.f16.f16 " \
        "{%0,%1},{%2,%3,%4,%5},{%6,%7},{%0,%1};" \
        : "+r"((d)[0]),"+r"((d)[1]) \
        : "r"((a)[0]),"r"((a)[1]),"r"((a)[2]),"r"((a)[3]), "r"(b0),"r"(b1))

__device__ __forceinline__ uint32_t f2h2(float x, float y){
    __half2 h = __floats2half2_rn(x, y);
    return *(uint32_t*)&h;
}
__device__ __forceinline__ void split_pair_h(float x, float y, uint32_t& h2, uint32_t& l2){
    h2 = f2h2(x, y);
    float2 f = __half22float2(*(__half2*)&h2);
    l2 = f2h2(x - f.x, y - f.y);
}
// fast e^x on FMA/ALU pipes. valid for x <= 0, clamps below -87. fast_exp(0)==1.0f exactly.
__device__ __forceinline__ float fast_exp(float x){
    x = fmaxf(x, -87.0f);
    float y = x * 1.4426950408889634f;
    float r = __fadd_rn(y, 12582912.0f);
    float f = y - __fadd_rn(r, -12582912.0f);
    float p = 1.5403530e-4f;
    p = __fmaf_rn(p, f, 1.3333558e-3f);
    p = __fmaf_rn(p, f, 9.6181291e-3f);
    p = __fmaf_rn(p, f, 5.5504109e-2f);
    p = __fmaf_rn(p, f, 2.4022651e-1f);
    p = __fmaf_rn(p, f, 6.9314718e-1f);
    p = __fmaf_rn(p, f, 1.0f);
    int n = __float_as_int(r) - 0x4B400000;
    return __int_as_float(__float_as_int(p) + (n << 23));
}

// ---------------- fused preprocessing: rope tables + hs split + weight cvt ---
// region A: blocks [0, 64)            rope tables (2048 elems/block)
// region B: blocks [64, 64+8192)      hs hi/lo split (2048 floats/block)
// region C: blocks [8256, 8256+20480) weight converts (2048 floats/block)
#define PRE_ROPE_BLKS 64
#define PRE_HS_BLKS   (TOK*H_/2048)                       // 8192
#define PRE_W_BLKS    ((QWN + 2*KWN + H_*H_)/2048)        // 20480
#define PRE_BLKS      (PRE_ROPE_BLKS + PRE_HS_BLKS + PRE_W_BLKS)

__global__ void preproc_kernel(const float* __restrict__ hs,
                               const float* __restrict__ Wq, const float* __restrict__ Wk,
                               const float* __restrict__ Wv, const float* __restrict__ Wo){
    int blk = blockIdx.x;
    if (blk < PRE_ROPE_BLKS){
        int idx0 = (blk << 11) + (threadIdx.x << 3);
        #pragma unroll
        for (int u = 0; u < 8; ++u){
            int idx = idx0 + u;
            int s = idx >> 6, j = idx & 63;
            double inv = pow(500000.0, -((double)j)/64.0);
            float ang = (float)s * (float)inv;
            g_cos[idx] = (float)cos((double)ang);
            g_sin[idx] = (float)sin((double)ang);
        }
        return;
    }
    blk -= PRE_ROPE_BLKS;
    if (blk < PRE_HS_BLKS){
        size_t i = (((size_t)blk << 8) + threadIdx.x) << 3;
        #pragma unroll
        for (int u = 0; u < 2; ++u){
            float4 v = *(const float4*)(hs + i + u*4);
            uint32_t h0, l0, h1, l1;
            split_pair_h(v.x, v.y, h0, l0);
            split_pair_h(v.z, v.w, h1, l1);
            *(uint32_t*)(g_hsH + i + u*4)     = h0;
            *(uint32_t*)(g_hsH + i + u*4 + 2) = h1;
            *(uint32_t*)(g_hsL + i + u*4)     = l0;
            *(uint32_t*)(g_hsL + i + u*4 + 2) = l1;
        }
        return;
    }
    blk -= PRE_HS_BLKS;
    size_t i = (((size_t)blk << 8) + threadIdx.x) << 3;
    const float* src; __half* dst; size_t off;
    if (i < QWN)              { src = Wq; dst = g_Wq; off = i; }
    else if (i < QWN + KWN)   { src = Wk; dst = g_Wk; off = i - QWN; }
    else if (i < QWN + 2*KWN) { src = Wv; dst = g_Wv; off = i - QWN - KWN; }
    else                      { src = Wo; dst = g_Wo; off = i - QWN - 2*KWN; }
    #pragma unroll
    for (int u = 0; u < 2; ++u){
        float4 v = *(const float4*)(src + off + u*4);
        *(uint32_t*)(dst + off + u*4)     = f2h2(v.x, v.y);
        *(uint32_t*)(dst + off + u*4 + 2) = f2h2(v.z, v.w);
    }
}

// ---------------- HMMA GEMM (fused QKV / O-proj), fp16 2-pass ----------------
// BM=128 BN=128 BK=64; 8 warps (4x2); 2-stage cp.async; 2 CTAs/SM.
#define BK_      64
#define ROWB     144                    // 128B data + 16B pad (conflict-free)
#define MATB     (128*ROWB)             // 18432
#define STGB     (3*MATB)               // 55296 (AH, AL, BH)
#define GSMEM    (2*STGB)               // 110592 (covers 67584B epilogue staging)
#define KTILES   (H_/BK_)               // 64

__device__ __forceinline__ void hmma_load_stage(
    uint32_t sb, int s, const __half* AH, const __half* AL, const __half* BH,
    int M0, int N0, int kt, int tid)
{
    uint32_t base = sb + s*STGB;
    #pragma unroll
    for (int i = 0; i < 12; ++i){
        int c = tid + (i << 8);          // 0..3071
        int mat = c >> 10;               // 0=AH 1=AL 2=BH
        int cc = c & 1023;
        int row = cc >> 3, ch = cc & 7;
        uint32_t soff = (uint32_t)mat*MATB + row*ROWB + (ch << 4);
        const __half* src = (mat == 0) ? AH : (mat == 1) ? AL : BH;
        int base_row = (mat == 2) ? N0 : M0;
        CP_ASYNC16(base + soff, src + (size_t)(base_row + row)*H_ + kt*BK_ + (ch << 3));
    }
}

// mode 0: fused QKV projections (blockIdx.x: 0-31 Q, 32-39 K, 40-47 V)
// mode 1: O projection -> Cout fp32
__global__ __launch_bounds__(256, 2)
void gemm_hmma_kernel(float* __restrict__ Cout, int mode)
{
    extern __shared__ char smem[];
    uint32_t sb = smem_to_u32(smem);
    const int tid = threadIdx.x;
    const int wid = tid >> 5, lane = tid & 31;
    const int wm = wid & 3, wn = wid >> 2;
    const int bx = blockIdx.x;
    const int M0 = blockIdx.y << 7;

    const __half *AH, *AL, *BH;
    int N0, dest, head = 0;
    if (mode == 1){
        AH = g_OH; AL = g_OL; BH = g_Wo;
        N0 = bx << 7; dest = 3;
    } else {
        AH = g_hsH; AL = g_hsL;
        if (bx < 32)      { BH = g_Wq; head = bx;      dest = 0; }
        else if (bx < 40) { BH = g_Wk; head = bx - 32; dest = 1; }
        else              { BH = g_Wv; head = bx - 40; dest = 2; }
        N0 = head << 7;
    }

    float acc[2][8][4];
    #pragma unroll
    for (int m = 0; m < 2; ++m)
        #pragma unroll
        for (int n = 0; n < 8; ++n)
            #pragma unroll
            for (int j = 0; j < 4; ++j) acc[m][n][j] = 0.f;

    hmma_load_stage(sb, 0, AH, AL, BH, M0, N0, 0, tid); CP_COMMIT();

    const uint32_t aRow = (uint32_t)(wm*32 + (lane & 15));
    const uint32_t aColB = (uint32_t)(((lane >> 4) << 3) * 2);
    const uint32_t bRow = (uint32_t)(wn*64 + ((lane & 7) | ((lane & 16) >> 1)));
    const uint32_t bColB = (uint32_t)((((lane >> 3) & 1) << 3) * 2);

    #pragma unroll 1
    for (int kt = 0; kt < KTILES; ++kt){
        const int s = kt & 1;
        CP_WAIT0();
        __syncthreads();
        if (kt + 1 < KTILES){
            hmma_load_stage(sb, s^1, AH, AL, BH, M0, N0, kt + 1, tid);
            CP_COMMIT();
        }

        const uint32_t stA = sb + s*STGB;
        const uint32_t stB = stA + 2*MATB;
        #pragma unroll
        for (int ks = 0; ks < 4; ++ks){
            const uint32_t kB = (uint32_t)(ks << 5);      // 16 fp16 = 32B per k-step
            uint32_t aHr[2][4], aLr[2][4];
            #pragma unroll
            for (int mm = 0; mm < 2; ++mm){
                uint32_t off = (aRow + mm*16)*ROWB + kB + aColB;
                LDSM_X4(aHr[mm], stA + off);
                LDSM_X4(aLr[mm], stA + MATB + off);
            }
            #pragma unroll
            for (int g = 0; g < 4; ++g){
                uint32_t bH[4];
                uint32_t off = (bRow + g*16)*ROWB + kB + bColB;
                LDSM_X4(bH, stB + off);
                MMA_F16(acc[0][2*g],   aHr[0], bH[0], bH[1]);
                MMA_F16(acc[0][2*g+1], aHr[0], bH[2], bH[3]);
                MMA_F16(acc[1][2*g],   aHr[1], bH[0], bH[1]);
                MMA_F16(acc[1][2*g+1], aHr[1], bH[2], bH[3]);
                MMA_F16(acc[0][2*g],   aLr[0], bH[0], bH[1]);
                MMA_F16(acc[0][2*g+1], aLr[0], bH[2], bH[3]);
                MMA_F16(acc[1][2*g],   aLr[1], bH[0], bH[1]);
                MMA_F16(acc[1][2*g+1], aLr[1], bH[2], bH[3]);
            }
        }
    }

    // ---- epilogue ----
    const int rbase = wm*32 + (lane >> 2);
    const int cbase = wn*64 + (lane & 3)*2;
    if (dest == 3 || dest == 2){
        #pragma unroll
        for (int mm = 0; mm < 2; ++mm){
            #pragma unroll
            for (int half = 0; half < 2; ++half){
                int r = M0 + rbase + mm*16 + half*8;
                #pragma unroll
                for (int nn = 0; nn < 8; ++nn){
                    float vx = acc[mm][nn][half*2];
                    float vy = acc[mm][nn][half*2 + 1];
                    if (dest == 3){
                        float2 v; v.x = vx; v.y = vy;
                        *(float2*)(Cout + (size_t)r*H_ + N0 + cbase + nn*8) = v;
                    } else {
                        int bb = r >> 11, ss = r & (S_ - 1);
                        size_t idx = (((size_t)bb*NKV_ + head)*S_ + ss)*HD_ + cbase + nn*8;
                        *(uint32_t*)(g_Vb + idx) = f2h2(vx, vy);
                    }
                }
            }
        }
    } else {
        // Q or K: stage tile in smem, apply RoPE (+scale for Q), write fp16 (paired 4B stores)
        __syncthreads();
        float* sm32 = (float*)smem;
        #pragma unroll
        for (int mm = 0; mm < 2; ++mm){
            #pragma unroll
            for (int half = 0; half < 2; ++half){
                int rl = rbase + mm*16 + half*8;
                #pragma unroll
                for (int nn = 0; nn < 8; ++nn){
                    float2 v;
                    v.x = acc[mm][nn][half*2];
                    v.y = acc[mm][nn][half*2 + 1];
                    *(float2*)(sm32 + rl*132 + cbase + nn*8) = v;
                }
            }
        }
        __syncthreads();
        const float qsc = 0.08838834764831845f;
        #pragma unroll 4
        for (int i = tid; i < 128*32; i += 256){
            int r = i >> 5, jp = (i & 31) << 1;
            int token = M0 + r;
            int bb = token >> 11, ss = token & (S_ - 1);
            float ca = g_cos[(ss << 6) + jp],     sa = g_sin[(ss << 6) + jp];
            float cb = g_cos[(ss << 6) + jp + 1], sb2 = g_sin[(ss << 6) + jp + 1];
            float x1a = sm32[r*132 + jp],      x1b = sm32[r*132 + jp + 1];
            float x2a = sm32[r*132 + jp + 64], x2b = sm32[r*132 + jp + 65];
            float y1a = x1a*ca - x2a*sa,  y1b = x1b*cb - x2b*sb2;
            float y2a = x2a*ca + x1a*sa,  y2b = x2b*cb + x1b*sb2;
            if (dest == 0){
                y1a *= qsc; y1b *= qsc; y2a *= qsc; y2b *= qsc;
                size_t base = (((size_t)bb*NH_ + head)*S_ + ss)*HD_;
                uint32_t h2a, l2a, h2b, l2b;
                split_pair_h(y1a, y1b, h2a, l2a);
                split_pair_h(y2a, y2b, h2b, l2b);
                *(uint32_t*)(g_QbH + base + jp)      = h2a;
                *(uint32_t*)(g_QbH + base + jp + 64) = h2b;
                *(uint32_t*)(g_QbL + base + jp)      = l2a;
                *(uint32_t*)(g_QbL + base + jp + 64) = l2b;
            } else {
                size_t base = (((size_t)bb*NKV_ + head)*S_ + ss)*HD_;
                *(uint32_t*)(g_Kb + base + jp)      = f2h2(y1a, y1b);
                *(uint32_t*)(g_Kb + base + jp + 64) = f2h2(y2a, y2b);
            }
        }
    }
}

// ---------------- HMMA flash attention (fp16 2-pass, 2-stage 32-key KV) -----
// 256 threads, 8 warps, Q-tile 128 rows, KV-tile 32 keys, 2 CTAs/SM.
// QK lo-pass uses f16-accumulator HMMA (rate probe), folded into fp32 after.
#define AROWB 272
#define AQMAT (128*AROWB)               // 34816
#define AKMAT (32*AROWB)                // 8704
#define ASTGB (2*AKMAT)                 // K + V = 17408
#define ASMEM (2*AQMAT + 2*ASTGB)       // 104448 -> 2 CTAs/SM
#define NKB   (S_/32)                   // 64

__device__ __forceinline__ void attn_load_kv(
    uint32_t st, const __half* Kg, const __half* Vg, int key0, int tid)
{
    #pragma unroll
    for (int i = 0; i < 4; ++i){
        int c = tid + (i << 8);          // 0..1023
        int mat = c >> 9;                // 0=K 1=V (512 chunks each)
        int cc = c & 511;
        int row = cc >> 4, ch = cc & 15;
        uint32_t dst = st + (uint32_t)mat*AKMAT + row*AROWB + (ch << 4);
        const __half* src = mat ? Vg : Kg;
        CP_ASYNC16(dst, src + (size_t)(key0 + row)*HD_ + (ch << 3));
    }
}

__global__ __launch_bounds__(256, 2)
void attn_mma_kernel(){
    extern __shared__ char smem[];
    uint32_t sb = smem_to_u32(smem);
    const int tid = threadIdx.x;
    const int wid = tid >> 5, lane = tid & 31;
    const int qb = blockIdx.x, h = blockIdx.y, b = blockIdx.z;
    const int g = h >> 2;

    const __half* QHg = g_QbH + (((size_t)b*NH_ + h)*S_ + (size_t)qb*128)*HD_;
    const __half* QLg = g_QbL + (((size_t)b*NH_ + h)*S_ + (size_t)qb*128)*HD_;
    const __half* Kg  = g_Kb + ((size_t)b*NKV_ + g)*S_*HD_;
    const __half* Vg  = g_Vb + ((size_t)b*NKV_ + g)*S_*HD_;

    const uint32_t QH0 = sb, QL0 = sb + AQMAT;
    const uint32_t KVB = sb + 2*AQMAT;

    #pragma unroll
    for (int i = 0; i < 16; ++i){
        int c = tid + (i << 8);
        int mat = c >> 11;
        int cc = c & 2047;
        int row = cc >> 4, ch = cc & 15;
        uint32_t dst = (mat ? QL0 : QH0) + row*AROWB + (ch << 4);
        const __half* src = mat ? QLg : QHg;
        CP_ASYNC16(dst, src + (size_t)row*HD_ + (ch << 3));
    }
    attn_load_kv(KVB, Kg, Vg, 0, tid);
    CP_COMMIT();

    float m0 = -1e30f, m1 = -1e30f, l0 = 0.f, l1 = 0.f;
    float O[16][4];
    #pragma unroll
    for (int nt = 0; nt < 16; ++nt)
        #pragma unroll
        for (int j = 0; j < 4; ++j) O[nt][j] = 0.f;

    const uint32_t aOff  = (uint32_t)(wid*16 + (lane & 15))*AROWB + ((lane >> 4) << 4);
    const uint32_t bOffK = (uint32_t)((lane & 7) | ((lane & 16) >> 1))*AROWB + (((lane >> 3) & 1) << 4);
    const uint32_t vOff  = (uint32_t)((lane & 7) + (lane & 8))*AROWB + ((lane >> 4) << 4);

    #pragma unroll 1
    for (int kb = 0; kb < NKB; ++kb){
        const int s = kb & 1;
        const uint32_t Kst = KVB + s*ASTGB;
        const uint32_t Vst = Kst + AKMAT;

        CP_WAIT0();
        __syncthreads();
        if (kb + 1 < NKB){
            attn_load_kv(KVB + (s^1)*ASTGB, Kg, Vg, (kb+1)*32, tid);
            CP_COMMIT();
        }

        // ---- S = Q K^T: hi pass fp32-acc, lo pass f16-acc (folded after) ----
        float Sa[4][4];
        uint32_t SaLo[4][2];
        #pragma unroll
        for (int nt = 0; nt < 4; ++nt){
            #pragma unroll
            for (int j = 0; j < 4; ++j) Sa[nt][j] = 0.f;
            SaLo[nt][0] = 0u; SaLo[nt][1] = 0u;
        }

        #pragma unroll
        for (int ks = 0; ks < 8; ++ks){
            uint32_t aH[4], aL[4];
            LDSM_X4(aH, QH0 + aOff + ks*32);
            LDSM_X4(aL, QL0 + aOff + ks*32);
            #pragma unroll
            for (int gi = 0; gi < 2; ++gi){
                uint32_t bK[4];
                LDSM_X4(bK, Kst + bOffK + gi*(16*AROWB) + ks*32);
                MMA_F16(Sa[2*gi],   aH, bK[0], bK[1]);
                MMA_F16(Sa[2*gi+1], aH, bK[2], bK[3]);
                MMA_F16ACC(SaLo[2*gi],   aL, bK[0], bK[1]);
                MMA_F16ACC(SaLo[2*gi+1], aL, bK[2], bK[3]);
            }
        }
        // fold lo into hi
        #pragma unroll
        for (int nt = 0; nt < 4; ++nt){
            float2 lo0 = __half22float2(*(__half2*)&SaLo[nt][0]);
            float2 lo1 = __half22float2(*(__half2*)&SaLo[nt][1]);
            Sa[nt][0] += lo0.x; Sa[nt][1] += lo0.y;
            Sa[nt][2] += lo1.x; Sa[nt][3] += lo1.y;
        }

        // ---- online softmax ----
        float mb0 = -1e30f, mb1 = -1e30f;
        #pragma unroll
        for (int nt = 0; nt < 4; ++nt){
            mb0 = fmaxf(mb0, fmaxf(Sa[nt][0], Sa[nt][1]));
            mb1 = fmaxf(mb1, fmaxf(Sa[nt][2], Sa[nt][3]));
        }
        mb0 = fmaxf(mb0, __shfl_xor_sync(0xffffffffu, mb0, 1));
        mb0 = fmaxf(mb0, __shfl_xor_sync(0xffffffffu, mb0, 2));
        mb1 = fmaxf(mb1, __shfl_xor_sync(0xffffffffu, mb1, 1));
        mb1 = fmaxf(mb1, __shfl_xor_sync(0xffffffffu, mb1, 2));
        float m0n = fmaxf(m0, mb0), m1n = fmaxf(m1, mb1);
        float corr0 = fast_exp(m0 - m0n), corr1 = fast_exp(m1 - m1n);
        m0 = m0n; m1 = m1n;

        float ls0 = 0.f, ls1 = 0.f;
        #pragma unroll
        for (int nt = 0; nt < 4; ++nt){
            Sa[nt][0] = fast_exp(Sa[nt][0] - m0);
            Sa[nt][1] = fast_exp(Sa[nt][1] - m0);
            Sa[nt][2] = fast_exp(Sa[nt][2] - m1);
            Sa[nt][3] = fast_exp(Sa[nt][3] - m1);
            ls0 += Sa[nt][0] + Sa[nt][1];
            ls1 += Sa[nt][2] + Sa[nt][3];
        }
        ls0 += __shfl_xor_sync(0xffffffffu, ls0, 1);
        ls0 += __shfl_xor_sync(0xffffffffu, ls0, 2);
        ls1 += __shfl_xor_sync(0xffffffffu, ls1, 1);
        ls1 += __shfl_xor_sync(0xffffffffu, ls1, 2);
        l0 = l0*corr0 + ls0;
        l1 = l1*corr1 + ls1;

        // skip the rescale when corr == 1 exactly (bit-identical: x*1 == x)
        if (!__all_sync(0xffffffffu, (corr0 == 1.0f) && (corr1 == 1.0f))){
            #pragma unroll
            for (int nt = 0; nt < 16; ++nt){
                O[nt][0] *= corr0; O[nt][1] *= corr0;
                O[nt][2] *= corr1; O[nt][3] *= corr1;
            }
        }

        // ---- P -> A fragments (fp16 hi/lo) ----
        uint32_t aPh[2][4], aPl[2][4];
        #pragma unroll
        for (int kt = 0; kt < 2; ++kt){
            split_pair_h(Sa[2*kt][0],   Sa[2*kt][1],   aPh[kt][0], aPl[kt][0]);
            split_pair_h(Sa[2*kt][2],   Sa[2*kt][3],   aPh[kt][1], aPl[kt][1]);
            split_pair_h(Sa[2*kt+1][0], Sa[2*kt+1][1], aPh[kt][2], aPl[kt][2]);
            split_pair_h(Sa[2*kt+1][2], Sa[2*kt+1][3], aPh[kt][3], aPl[kt][3]);
        }

        // ---- O += P V (2-pass fp16, V via ldmatrix.trans) ----
        #pragma unroll
        for (int kt = 0; kt < 2; ++kt){
            #pragma unroll
            for (int dp = 0; dp < 8; ++dp){
                uint32_t bV[4];
                LDSM_X4_T(bV, Vst + vOff + kt*(16*AROWB) + dp*32);
                MMA_F16(O[2*dp],   aPh[kt], bV[0], bV[1]);
                MMA_F16(O[2*dp+1], aPh[kt], bV[2], bV[3]);
                MMA_F16(O[2*dp],   aPl[kt], bV[0], bV[1]);
                MMA_F16(O[2*dp+1], aPl[kt], bV[2], bV[3]);
            }
        }
    }

    // ---- epilogue: normalize, fp16 hi/lo to g_OH/g_OL ----
    const float inv0 = 1.0f / l0, inv1 = 1.0f / l1;
    const int s0 = qb*128 + wid*16 + (lane >> 2);
    const size_t ob = (size_t)b*S_*H_ + (size_t)h*HD_;
    #pragma unroll
    for (int nt = 0; nt < 16; ++nt){
        int d = nt*8 + (lane & 3)*2;
        uint32_t h2, l2;
        split_pair_h(O[nt][0]*inv0, O[nt][1]*inv0, h2, l2);
        size_t idx0 = ob + (size_t)s0*H_ + d;
        *(uint32_t*)(g_OH + idx0) = h2;
        *(uint32_t*)(g_OL + idx0) = l2;
        split_pair_h(O[nt][2]*inv1, O[nt][3]*inv1, h2, l2);
        size_t idx1 = ob + (size_t)(s0 + 8)*H_ + d;
        *(uint32_t*)(g_OH + idx1) = h2;
        *(uint32_t*)(g_OL + idx1) = l2;
    }
}

// ---------------- launch ----------------------------------------------------
extern "C" void kernel_launch(void* const* d_in, const int* in_sizes, int n_in,
                              void* d_out, int out_size)
{
    const float* hs = (const float*)d_in[0];
    const float* Wq = (const float*)d_in[1];
    const float* Wk = (const float*)d_in[2];
    const float* Wv = (const float*)d_in[3];
    const float* Wo = (const float*)d_in[4];
    float* out = (float*)d_out;

    // fused preprocessing (rope tables + hs split + weight converts)
    preproc_kernel<<<PRE_BLKS, 256>>>(hs, Wq, Wk, Wv, Wo);

    cudaFuncSetAttribute(gemm_hmma_kernel, cudaFuncAttributeMaxDynamicSharedMemorySize, GSMEM);
    cudaFuncSetAttribute(attn_mma_kernel, cudaFuncAttributeMaxDynamicSharedMemorySize, ASMEM);

    // fused Q/K/V projections with RoPE + fp16 conversion in epilogue
    gemm_hmma_kernel<<<dim3(48, 32), 256, GSMEM>>>(nullptr, 0);

    // flash attention (128-row Q tiles, 32-key KV tiles, 2 CTAs/SM)
    attn_mma_kernel<<<dim3(S_/128, NH_, B_), 256, ASMEM>>>();

    // output projection -> d_out
    gemm_hmma_kernel<<<dim3(32, 32), 256, GSMEM>>>(out, 1);
}

// round 14
// speedup vs baseline: 1.2122x; 1.0591x over previous
#include <cuda_runtime.h>
#include <cuda_fp16.h>
#include <math.h>
#include <stdint.h>

#define B_   2
#define S_   2048
#define H_   4096
#define NH_  32
#define NKV_ 8
#define HD_  128
#define TOK  (B_*S_)        // 4096
#define QWN  (NH_*HD_*H_)   // 16777216
#define KWN  (NKV_*HD_*H_)  // 4194304

// ---------------- scratch (static device globals; no allocation) ----------
__device__ float g_cos[S_*64];
__device__ float g_sin[S_*64];

// fp16 operands
__device__ __half g_hsH[(size_t)TOK*H_], g_hsL[(size_t)TOK*H_];
__device__ __half g_Wq[(size_t)QWN];
__device__ __half g_Wk[(size_t)KWN];
__device__ __half g_Wv[(size_t)KWN];
__device__ __half g_Wo[(size_t)H_*H_];
__device__ __half g_OH[(size_t)TOK*H_], g_OL[(size_t)TOK*H_];

// attention operands (fp16; RoPE and scale pre-applied)
__device__ __half g_QbH[(size_t)B_*NH_*S_*HD_], g_QbL[(size_t)B_*NH_*S_*HD_];
__device__ __half g_Kb[(size_t)B_*NKV_*S_*HD_];
__device__ __half g_Vb[(size_t)B_*NKV_*S_*HD_];

// ---------------- helpers ----------------------------------------------------
__device__ __forceinline__ uint32_t smem_to_u32(const void* p){
    uint32_t a;
    asm("{ .reg .u64 t; cvta.to.shared.u64 t, %1; cvt.u32.u64 %0, t; }" : "=r"(a) : "l"(p));
    return a;
}
#define CP_ASYNC16(dst, src) \
    asm volatile("cp.async.cg.shared.global [%0], [%1], 16;" :: "r"(dst), "l"(src))
#define CP_COMMIT() asm volatile("cp.async.commit_group;" ::: "memory")
#define CP_WAIT0()  asm volatile("cp.async.wait_group 0;" ::: "memory")

#define LDSM_X4(r, addr) \
    asm volatile("ldmatrix.sync.aligned.m8n8.x4.shared.b16 {%0,%1,%2,%3}, [%4];" \
        : "=r"((r)[0]),"=r"((r)[1]),"=r"((r)[2]),"=r"((r)[3]) : "r"(addr))
#define LDSM_X4_T(r, addr) \
    asm volatile("ldmatrix.sync.aligned.m8n8.x4.trans.shared.b16 {%0,%1,%2,%3}, [%4];" \
        : "=r"((r)[0]),"=r"((r)[1]),"=r"((r)[2]),"=r"((r)[3]) : "r"(addr))

#define MMA_F16(c, a, b0, b1) \
    asm volatile("mma.sync.aligned.m16n8k16.row.col.f32.f16.f16.f32 " \
        "{%0,%1,%2,%3},{%4,%5,%6,%7},{%8,%9},{%0,%1,%2,%3};" \
        : "+f"((c)[0]),"+f"((c)[1]),"+f"((c)[2]),"+f"((c)[3]) \
        : "r"((a)[0]),"r"((a)[1]),"r"((a)[2]),"r"((a)[3]), "r"(b0),"r"(b1))

// f16-accumulator HMMA: D = {d0,d1} packed half2 (c0,c1) and (c2,c3)
#define MMA_F16ACC(d, a, b0, b1) \
    asm volatile("mma.sync.aligned.m16n8k16.row.col.f16.f16.f16.f16 " \
        "{%0,%1},{%2,%3,%4,%5},{%6,%7},{%0,%1};" \
        : "+r"((d)[0]),"+r"((d)[1]) \
        : "r"((a)[0]),"r"((a)[1]),"r"((a)[2]),"r"((a)[3]), "r"(b0),"r"(b1))

__device__ __forceinline__ uint32_t f2h2(float x, float y){
    __half2 h = __floats2half2_rn(x, y);
    return *(uint32_t*)&h;
}
__device__ __forceinline__ void split_pair_h(float x, float y, uint32_t& h2, uint32_t& l2){
    h2 = f2h2(x, y);
    float2 f = __half22float2(*(__half2*)&h2);
    l2 = f2h2(x - f.x, y - f.y);
}
// fast e^x on FMA/ALU pipes. valid for x <= 0, clamps below -87. fast_exp(0)==1.0f exactly.
__device__ __forceinline__ float fast_exp(float x){
    x = fmaxf(x, -87.0f);
    float y = x * 1.4426950408889634f;
    float r = __fadd_rn(y, 12582912.0f);
    float f = y - __fadd_rn(r, -12582912.0f);
    float p = 1.5403530e-4f;
    p = __fmaf_rn(p, f, 1.3333558e-3f);
    p = __fmaf_rn(p, f, 9.6181291e-3f);
    p = __fmaf_rn(p, f, 5.5504109e-2f);
    p = __fmaf_rn(p, f, 2.4022651e-1f);
    p = __fmaf_rn(p, f, 6.9314718e-1f);
    p = __fmaf_rn(p, f, 1.0f);
    int n = __float_as_int(r) - 0x4B400000;
    return __int_as_float(__float_as_int(p) + (n << 23));
}

// ---------------- fused preprocessing: rope tables + hs split + weight cvt ---
#define PRE_ROPE_BLKS 64
#define PRE_HS_BLKS   (TOK*H_/2048)                       // 8192
#define PRE_W_BLKS    ((QWN + 2*KWN + H_*H_)/2048)        // 20480
#define PRE_BLKS      (PRE_ROPE_BLKS + PRE_HS_BLKS + PRE_W_BLKS)

__global__ void preproc_kernel(const float* __restrict__ hs,
                               const float* __restrict__ Wq, const float* __restrict__ Wk,
                               const float* __restrict__ Wv, const float* __restrict__ Wo){
    int blk = blockIdx.x;
    if (blk < PRE_ROPE_BLKS){
        int idx0 = (blk << 11) + (threadIdx.x << 3);
        #pragma unroll
        for (int u = 0; u < 8; ++u){
            int idx = idx0 + u;
            int s = idx >> 6, j = idx & 63;
            double inv = pow(500000.0, -((double)j)/64.0);
            float ang = (float)s * (float)inv;
            g_cos[idx] = (float)cos((double)ang);
            g_sin[idx] = (float)sin((double)ang);
        }
        return;
    }
    blk -= PRE_ROPE_BLKS;
    if (blk < PRE_HS_BLKS){
        size_t i = (((size_t)blk << 8) + threadIdx.x) << 3;
        #pragma unroll
        for (int u = 0; u < 2; ++u){
            float4 v = *(const float4*)(hs + i + u*4);
            uint32_t h0, l0, h1, l1;
            split_pair_h(v.x, v.y, h0, l0);
            split_pair_h(v.z, v.w, h1, l1);
            *(uint32_t*)(g_hsH + i + u*4)     = h0;
            *(uint32_t*)(g_hsH + i + u*4 + 2) = h1;
            *(uint32_t*)(g_hsL + i + u*4)     = l0;
            *(uint32_t*)(g_hsL + i + u*4 + 2) = l1;
        }
        return;
    }
    blk -= PRE_HS_BLKS;
    size_t i = (((size_t)blk << 8) + threadIdx.x) << 3;
    const float* src; __half* dst; size_t off;
    if (i < QWN)              { src = Wq; dst = g_Wq; off = i; }
    else if (i < QWN + KWN)   { src = Wk; dst = g_Wk; off = i - QWN; }
    else if (i < QWN + 2*KWN) { src = Wv; dst = g_Wv; off = i - QWN - KWN; }
    else                      { src = Wo; dst = g_Wo; off = i - QWN - 2*KWN; }
    #pragma unroll
    for (int u = 0; u < 2; ++u){
        float4 v = *(const float4*)(src + off + u*4);
        *(uint32_t*)(dst + off + u*4)     = f2h2(v.x, v.y);
        *(uint32_t*)(dst + off + u*4 + 2) = f2h2(v.z, v.w);
    }
}

// ---------------- HMMA GEMM (fused QKV / O-proj), fp16 2-pass ----------------
// BM=128 BN=128 BK=64; 8 warps (4x2); 2-stage cp.async; 2 CTAs/SM.
#define BK_      64
#define ROWB     144
#define MATB     (128*ROWB)             // 18432
#define STGB     (3*MATB)               // 55296 (AH, AL, BH)
#define GSMEM    (2*STGB)               // 110592
#define KTILES   (H_/BK_)               // 64

__device__ __forceinline__ void hmma_load_stage(
    uint32_t sb, int s, const __half* AH, const __half* AL, const __half* BH,
    int M0, int N0, int kt, int tid)
{
    uint32_t base = sb + s*STGB;
    #pragma unroll
    for (int i = 0; i < 12; ++i){
        int c = tid + (i << 8);
        int mat = c >> 10;
        int cc = c & 1023;
        int row = cc >> 3, ch = cc & 7;
        uint32_t soff = (uint32_t)mat*MATB + row*ROWB + (ch << 4);
        const __half* src = (mat == 0) ? AH : (mat == 1) ? AL : BH;
        int base_row = (mat == 2) ? N0 : M0;
        CP_ASYNC16(base + soff, src + (size_t)(base_row + row)*H_ + kt*BK_ + (ch << 3));
    }
}

__global__ __launch_bounds__(256, 2)
void gemm_hmma_kernel(float* __restrict__ Cout, int mode)
{
    extern __shared__ char smem[];
    uint32_t sb = smem_to_u32(smem);
    const int tid = threadIdx.x;
    const int wid = tid >> 5, lane = tid & 31;
    const int wm = wid & 3, wn = wid >> 2;
    const int bx = blockIdx.x;
    const int M0 = blockIdx.y << 7;

    const __half *AH, *AL, *BH;
    int N0, dest, head = 0;
    if (mode == 1){
        AH = g_OH; AL = g_OL; BH = g_Wo;
        N0 = bx << 7; dest = 3;
    } else {
        AH = g_hsH; AL = g_hsL;
        if (bx < 32)      { BH = g_Wq; head = bx;      dest = 0; }
        else if (bx < 40) { BH = g_Wk; head = bx - 32; dest = 1; }
        else              { BH = g_Wv; head = bx - 40; dest = 2; }
        N0 = head << 7;
    }

    float acc[2][8][4];
    #pragma unroll
    for (int m = 0; m < 2; ++m)
        #pragma unroll
        for (int n = 0; n < 8; ++n)
            #pragma unroll
            for (int j = 0; j < 4; ++j) acc[m][n][j] = 0.f;

    hmma_load_stage(sb, 0, AH, AL, BH, M0, N0, 0, tid); CP_COMMIT();

    const uint32_t aRow = (uint32_t)(wm*32 + (lane & 15));
    const uint32_t aColB = (uint32_t)(((lane >> 4) << 3) * 2);
    const uint32_t bRow = (uint32_t)(wn*64 + ((lane & 7) | ((lane & 16) >> 1)));
    const uint32_t bColB = (uint32_t)((((lane >> 3) & 1) << 3) * 2);

    #pragma unroll 1
    for (int kt = 0; kt < KTILES; ++kt){
        const int s = kt & 1;
        CP_WAIT0();
        __syncthreads();
        if (kt + 1 < KTILES){
            hmma_load_stage(sb, s^1, AH, AL, BH, M0, N0, kt + 1, tid);
            CP_COMMIT();
        }

        const uint32_t stA = sb + s*STGB;
        const uint32_t stB = stA + 2*MATB;
        #pragma unroll
        for (int ks = 0; ks < 4; ++ks){
            const uint32_t kB = (uint32_t)(ks << 5);
            uint32_t aHr[2][4], aLr[2][4];
            #pragma unroll
            for (int mm = 0; mm < 2; ++mm){
                uint32_t off = (aRow + mm*16)*ROWB + kB + aColB;
                LDSM_X4(aHr[mm], stA + off);
                LDSM_X4(aLr[mm], stA + MATB + off);
            }
            #pragma unroll
            for (int g = 0; g < 4; ++g){
                uint32_t bH[4];
                uint32_t off = (bRow + g*16)*ROWB + kB + bColB;
                LDSM_X4(bH, stB + off);
                MMA_F16(acc[0][2*g],   aHr[0], bH[0], bH[1]);
                MMA_F16(acc[0][2*g+1], aHr[0], bH[2], bH[3]);
                MMA_F16(acc[1][2*g],   aHr[1], bH[0], bH[1]);
                MMA_F16(acc[1][2*g+1], aHr[1], bH[2], bH[3]);
                MMA_F16(acc[0][2*g],   aLr[0], bH[0], bH[1]);
                MMA_F16(acc[0][2*g+1], aLr[0], bH[2], bH[3]);
                MMA_F16(acc[1][2*g],   aLr[1], bH[0], bH[1]);
                MMA_F16(acc[1][2*g+1], aLr[1], bH[2], bH[3]);
            }
        }
    }

    // ---- epilogue ----
    const int rbase = wm*32 + (lane >> 2);
    const int cbase = wn*64 + (lane & 3)*2;
    if (dest == 3 || dest == 2){
        #pragma unroll
        for (int mm = 0; mm < 2; ++mm){
            #pragma unroll
            for (int half = 0; half < 2; ++half){
                int r = M0 + rbase + mm*16 + half*8;
                #pragma unroll
                for (int nn = 0; nn < 8; ++nn){
                    float vx = acc[mm][nn][half*2];
                    float vy = acc[mm][nn][half*2 + 1];
                    if (dest == 3){
                        float2 v; v.x = vx; v.y = vy;
                        *(float2*)(Cout + (size_t)r*H_ + N0 + cbase + nn*8) = v;
                    } else {
                        int bb = r >> 11, ss = r & (S_ - 1);
                        size_t idx = (((size_t)bb*NKV_ + head)*S_ + ss)*HD_ + cbase + nn*8;
                        *(uint32_t*)(g_Vb + idx) = f2h2(vx, vy);
                    }
                }
            }
        }
    } else {
        __syncthreads();
        float* sm32 = (float*)smem;
        #pragma unroll
        for (int mm = 0; mm < 2; ++mm){
            #pragma unroll
            for (int half = 0; half < 2; ++half){
                int rl = rbase + mm*16 + half*8;
                #pragma unroll
                for (int nn = 0; nn < 8; ++nn){
                    float2 v;
                    v.x = acc[mm][nn][half*2];
                    v.y = acc[mm][nn][half*2 + 1];
                    *(float2*)(sm32 + rl*132 + cbase + nn*8) = v;
                }
            }
        }
        __syncthreads();
        const float qsc = 0.08838834764831845f;
        #pragma unroll 4
        for (int i = tid; i < 128*32; i += 256){
            int r = i >> 5, jp = (i & 31) << 1;
            int token = M0 + r;
            int bb = token >> 11, ss = token & (S_ - 1);
            float ca = g_cos[(ss << 6) + jp],     sa = g_sin[(ss << 6) + jp];
            float cb = g_cos[(ss << 6) + jp + 1], sb2 = g_sin[(ss << 6) + jp + 1];
            float x1a = sm32[r*132 + jp],      x1b = sm32[r*132 + jp + 1];
            float x2a = sm32[r*132 + jp + 64], x2b = sm32[r*132 + jp + 65];
            float y1a = x1a*ca - x2a*sa,  y1b = x1b*cb - x2b*sb2;
            float y2a = x2a*ca + x1a*sa,  y2b = x2b*cb + x1b*sb2;
            if (dest == 0){
                y1a *= qsc; y1b *= qsc; y2a *= qsc; y2b *= qsc;
                size_t base = (((size_t)bb*NH_ + head)*S_ + ss)*HD_;
                uint32_t h2a, l2a, h2b, l2b;
                split_pair_h(y1a, y1b, h2a, l2a);
                split_pair_h(y2a, y2b, h2b, l2b);
                *(uint32_t*)(g_QbH + base + jp)      = h2a;
                *(uint32_t*)(g_QbH + base + jp + 64) = h2b;
                *(uint32_t*)(g_QbL + base + jp)      = l2a;
                *(uint32_t*)(g_QbL + base + jp + 64) = l2b;
            } else {
                size_t base = (((size_t)bb*NKV_ + head)*S_ + ss)*HD_;
                *(uint32_t*)(g_Kb + base + jp)      = f2h2(y1a, y1b);
                *(uint32_t*)(g_Kb + base + jp + 64) = f2h2(y2a, y2b);
            }
        }
    }
}

// ---------------- HMMA flash attention (2-stage 32-key KV, single-pass PV) --
// 256 threads, 8 warps, Q-tile 128 rows, KV-tile 32 keys, 2 CTAs/SM.
// QK: hi pass fp32-acc + lo pass f16-acc. PV: single hi pass (P-lo dropped;
// fp16 relative precision 2^-11 bounds the added output error ~2.8e-4).
#define AROWB 272
#define AQMAT (128*AROWB)               // 34816
#define AKMAT (32*AROWB)                // 8704
#define ASTGB (2*AKMAT)                 // K + V = 17408
#define ASMEM (2*AQMAT + 2*ASTGB)       // 104448 -> 2 CTAs/SM
#define NKB   (S_/32)                   // 64

__device__ __forceinline__ void attn_load_kv(
    uint32_t st, const __half* Kg, const __half* Vg, int key0, int tid)
{
    #pragma unroll
    for (int i = 0; i < 4; ++i){
        int c = tid + (i << 8);
        int mat = c >> 9;
        int cc = c & 511;
        int row = cc >> 4, ch = cc & 15;
        uint32_t dst = st + (uint32_t)mat*AKMAT + row*AROWB + (ch << 4);
        const __half* src = mat ? Vg : Kg;
        CP_ASYNC16(dst, src + (size_t)(key0 + row)*HD_ + (ch << 3));
    }
}

__global__ __launch_bounds__(256, 2)
void attn_mma_kernel(){
    extern __shared__ char smem[];
    uint32_t sb = smem_to_u32(smem);
    const int tid = threadIdx.x;
    const int wid = tid >> 5, lane = tid & 31;
    const int qb = blockIdx.x, h = blockIdx.y, b = blockIdx.z;
    const int g = h >> 2;

    const __half* QHg = g_QbH + (((size_t)b*NH_ + h)*S_ + (size_t)qb*128)*HD_;
    const __half* QLg = g_QbL + (((size_t)b*NH_ + h)*S_ + (size_t)qb*128)*HD_;
    const __half* Kg  = g_Kb + ((size_t)b*NKV_ + g)*S_*HD_;
    const __half* Vg  = g_Vb + ((size_t)b*NKV_ + g)*S_*HD_;

    const uint32_t QH0 = sb, QL0 = sb + AQMAT;
    const uint32_t KVB = sb + 2*AQMAT;

    #pragma unroll
    for (int i = 0; i < 16; ++i){
        int c = tid + (i << 8);
        int mat = c >> 11;
        int cc = c & 2047;
        int row = cc >> 4, ch = cc & 15;
        uint32_t dst = (mat ? QL0 : QH0) + row*AROWB + (ch << 4);
        const __half* src = mat ? QLg : QHg;
        CP_ASYNC16(dst, src + (size_t)row*HD_ + (ch << 3));
    }
    attn_load_kv(KVB, Kg, Vg, 0, tid);
    CP_COMMIT();

    float m0 = -1e30f, m1 = -1e30f, l0 = 0.f, l1 = 0.f;
    float O[16][4];
    #pragma unroll
    for (int nt = 0; nt < 16; ++nt)
        #pragma unroll
        for (int j = 0; j < 4; ++j) O[nt][j] = 0.f;

    const uint32_t aOff  = (uint32_t)(wid*16 + (lane & 15))*AROWB + ((lane >> 4) << 4);
    const uint32_t bOffK = (uint32_t)((lane & 7) | ((lane & 16) >> 1))*AROWB + (((lane >> 3) & 1) << 4);
    const uint32_t vOff  = (uint32_t)((lane & 7) + (lane & 8))*AROWB + ((lane >> 4) << 4);

    #pragma unroll 1
    for (int kb = 0; kb < NKB; ++kb){
        const int s = kb & 1;
        const uint32_t Kst = KVB + s*ASTGB;
        const uint32_t Vst = Kst + AKMAT;

        CP_WAIT0();
        __syncthreads();
        if (kb + 1 < NKB){
            attn_load_kv(KVB + (s^1)*ASTGB, Kg, Vg, (kb+1)*32, tid);
            CP_COMMIT();
        }

        // ---- S = Q K^T: hi pass fp32-acc, lo pass f16-acc (folded after) ----
        float Sa[4][4];
        uint32_t SaLo[4][2];
        #pragma unroll
        for (int nt = 0; nt < 4; ++nt){
            #pragma unroll
            for (int j = 0; j < 4; ++j) Sa[nt][j] = 0.f;
            SaLo[nt][0] = 0u; SaLo[nt][1] = 0u;
        }

        #pragma unroll
        for (int ks = 0; ks < 8; ++ks){
            uint32_t aH[4], aL[4];
            LDSM_X4(aH, QH0 + aOff + ks*32);
            LDSM_X4(aL, QL0 + aOff + ks*32);
            #pragma unroll
            for (int gi = 0; gi < 2; ++gi){
                uint32_t bK[4];
                LDSM_X4(bK, Kst + bOffK + gi*(16*AROWB) + ks*32);
                MMA_F16(Sa[2*gi],   aH, bK[0], bK[1]);
                MMA_F16(Sa[2*gi+1], aH, bK[2], bK[3]);
                MMA_F16ACC(SaLo[2*gi],   aL, bK[0], bK[1]);
                MMA_F16ACC(SaLo[2*gi+1], aL, bK[2], bK[3]);
            }
        }
        #pragma unroll
        for (int nt = 0; nt < 4; ++nt){
            float2 lo0 = __half22float2(*(__half2*)&SaLo[nt][0]);
            float2 lo1 = __half22float2(*(__half2*)&SaLo[nt][1]);
            Sa[nt][0] += lo0.x; Sa[nt][1] += lo0.y;
            Sa[nt][2] += lo1.x; Sa[nt][3] += lo1.y;
        }

        // ---- online softmax ----
        float mb0 = -1e30f, mb1 = -1e30f;
        #pragma unroll
        for (int nt = 0; nt < 4; ++nt){
            mb0 = fmaxf(mb0, fmaxf(Sa[nt][0], Sa[nt][1]));
            mb1 = fmaxf(mb1, fmaxf(Sa[nt][2], Sa[nt][3]));
        }
        mb0 = fmaxf(mb0, __shfl_xor_sync(0xffffffffu, mb0, 1));
        mb0 = fmaxf(mb0, __shfl_xor_sync(0xffffffffu, mb0, 2));
        mb1 = fmaxf(mb1, __shfl_xor_sync(0xffffffffu, mb1, 1));
        mb1 = fmaxf(mb1, __shfl_xor_sync(0xffffffffu, mb1, 2));
        float m0n = fmaxf(m0, mb0), m1n = fmaxf(m1, mb1);
        float corr0 = fast_exp(m0 - m0n), corr1 = fast_exp(m1 - m1n);
        m0 = m0n; m1 = m1n;

        float ls0 = 0.f, ls1 = 0.f;
        #pragma unroll
        for (int nt = 0; nt < 4; ++nt){
            Sa[nt][0] = fast_exp(Sa[nt][0] - m0);
            Sa[nt][1] = fast_exp(Sa[nt][1] - m0);
            Sa[nt][2] = fast_exp(Sa[nt][2] - m1);
            Sa[nt][3] = fast_exp(Sa[nt][3] - m1);
            ls0 += Sa[nt][0] + Sa[nt][1];
            ls1 += Sa[nt][2] + Sa[nt][3];
        }
        ls0 += __shfl_xor_sync(0xffffffffu, ls0, 1);
        ls0 += __shfl_xor_sync(0xffffffffu, ls0, 2);
        ls1 += __shfl_xor_sync(0xffffffffu, ls1, 1);
        ls1 += __shfl_xor_sync(0xffffffffu, ls1, 2);
        l0 = l0*corr0 + ls0;
        l1 = l1*corr1 + ls1;

        if (!__all_sync(0xffffffffu, (corr0 == 1.0f) && (corr1 == 1.0f))){
            #pragma unroll
            for (int nt = 0; nt < 16; ++nt){
                O[nt][0] *= corr0; O[nt][1] *= corr0;
                O[nt][2] *= corr1; O[nt][3] *= corr1;
            }
        }

        // ---- P -> A fragments (fp16, single precision level) ----
        uint32_t aP[2][4];
        #pragma unroll
        for (int kt = 0; kt < 2; ++kt){
            aP[kt][0] = f2h2(Sa[2*kt][0],   Sa[2*kt][1]);
            aP[kt][1] = f2h2(Sa[2*kt][2],   Sa[2*kt][3]);
            aP[kt][2] = f2h2(Sa[2*kt+1][0], Sa[2*kt+1][1]);
            aP[kt][3] = f2h2(Sa[2*kt+1][2], Sa[2*kt+1][3]);
        }

        // ---- O += P V (single pass, V via ldmatrix.trans) ----
        #pragma unroll
        for (int kt = 0; kt < 2; ++kt){
            #pragma unroll
            for (int dp = 0; dp < 8; ++dp){
                uint32_t bV[4];
                LDSM_X4_T(bV, Vst + vOff + kt*(16*AROWB) + dp*32);
                MMA_F16(O[2*dp],   aP[kt], bV[0], bV[1]);
                MMA_F16(O[2*dp+1], aP[kt], bV[2], bV[3]);
            }
        }
    }

    // ---- epilogue: normalize, fp16 hi/lo to g_OH/g_OL ----
    const float inv0 = 1.0f / l0, inv1 = 1.0f / l1;
    const int s0 = qb*128 + wid*16 + (lane >> 2);
    const size_t ob = (size_t)b*S_*H_ + (size_t)h*HD_;
    #pragma unroll
    for (int nt = 0; nt < 16; ++nt){
        int d = nt*8 + (lane & 3)*2;
        uint32_t h2, l2;
        split_pair_h(O[nt][0]*inv0, O[nt][1]*inv0, h2, l2);
        size_t idx0 = ob + (size_t)s0*H_ + d;
        *(uint32_t*)(g_OH + idx0) = h2;
        *(uint32_t*)(g_OL + idx0) = l2;
        split_pair_h(O[nt][2]*inv1, O[nt][3]*inv1, h2, l2);
        size_t idx1 = ob + (size_t)(s0 + 8)*H_ + d;
        *(uint32_t*)(g_OH + idx1) = h2;
        *(uint32_t*)(g_OL + idx1) = l2;
    }
}

// ---------------- launch ----------------------------------------------------
extern "C" void kernel_launch(void* const* d_in, const int* in_sizes, int n_in,
                              void* d_out, int out_size)
{
    const float* hs = (const float*)d_in[0];
    const float* Wq = (const float*)d_in[1];
    const float* Wk = (const float*)d_in[2];
    const float* Wv = (const float*)d_in[3];
    const float* Wo = (const float*)d_in[4];
    float* out = (float*)d_out;

    preproc_kernel<<<PRE_BLKS, 256>>>(hs, Wq, Wk, Wv, Wo);

    cudaFuncSetAttribute(gemm_hmma_kernel, cudaFuncAttributeMaxDynamicSharedMemorySize, GSMEM);
    cudaFuncSetAttribute(attn_mma_kernel, cudaFuncAttributeMaxDynamicSharedMemorySize, ASMEM);

    gemm_hmma_kernel<<<dim3(48, 32), 256, GSMEM>>>(nullptr, 0);
    attn_mma_kernel<<<dim3(S_/128, NH_, B_), 256, ASMEM>>>();
    gemm_hmma_kernel<<<dim3(32, 32), 256, GSMEM>>>(out, 1);
}

// round 15
// speedup vs baseline: 1.2325x; 1.0168x over previous
#include <cuda_runtime.h>
#include <cuda_fp16.h>
#include <math.h>
#include <stdint.h>

#define B_   2
#define S_   2048
#define H_   4096
#define NH_  32
#define NKV_ 8
#define HD_  128
#define TOK  (B_*S_)        // 4096
#define QWN  (NH_*HD_*H_)   // 16777216
#define KWN  (NKV_*HD_*H_)  // 4194304

// ---------------- scratch (static device globals; no allocation) ----------
__device__ float g_cos[S_*64];
__device__ float g_sin[S_*64];

// fp16 operands
__device__ __half g_hsH[(size_t)TOK*H_], g_hsL[(size_t)TOK*H_];
__device__ __half g_Wq[(size_t)QWN];
__device__ __half g_Wk[(size_t)KWN];
__device__ __half g_Wv[(size_t)KWN];
__device__ __half g_Wo[(size_t)H_*H_];
__device__ __half g_OH[(size_t)TOK*H_];

// attention operands (fp16; RoPE and scale pre-applied)
__device__ __half g_QbH[(size_t)B_*NH_*S_*HD_], g_QbL[(size_t)B_*NH_*S_*HD_];
__device__ __half g_Kb[(size_t)B_*NKV_*S_*HD_];
__device__ __half g_Vb[(size_t)B_*NKV_*S_*HD_];

// ---------------- helpers ----------------------------------------------------
__device__ __forceinline__ uint32_t smem_to_u32(const void* p){
    uint32_t a;
    asm("{ .reg .u64 t; cvta.to.shared.u64 t, %1; cvt.u32.u64 %0, t; }" : "=r"(a) : "l"(p));
    return a;
}
#define CP_ASYNC16(dst, src) \
    asm volatile("cp.async.cg.shared.global [%0], [%1], 16;" :: "r"(dst), "l"(src))
#define CP_COMMIT() asm volatile("cp.async.commit_group;" ::: "memory")
#define CP_WAIT0()  asm volatile("cp.async.wait_group 0;" ::: "memory")

#define LDSM_X4(r, addr) \
    asm volatile("ldmatrix.sync.aligned.m8n8.x4.shared.b16 {%0,%1,%2,%3}, [%4];" \
        : "=r"((r)[0]),"=r"((r)[1]),"=r"((r)[2]),"=r"((r)[3]) : "r"(addr))
#define LDSM_X4_T(r, addr) \
    asm volatile("ldmatrix.sync.aligned.m8n8.x4.trans.shared.b16 {%0,%1,%2,%3}, [%4];" \
        : "=r"((r)[0]),"=r"((r)[1]),"=r"((r)[2]),"=r"((r)[3]) : "r"(addr))

#define MMA_F16(c, a, b0, b1) \
    asm volatile("mma.sync.aligned.m16n8k16.row.col.f32.f16.f16.f32 " \
        "{%0,%1,%2,%3},{%4,%5,%6,%7},{%8,%9},{%0,%1,%2,%3};" \
        : "+f"((c)[0]),"+f"((c)[1]),"+f"((c)[2]),"+f"((c)[3]) \
        : "r"((a)[0]),"r"((a)[1]),"r"((a)[2]),"r"((a)[3]), "r"(b0),"r"(b1))

// f16-accumulator HMMA
#define MMA_F16ACC(d, a, b0, b1) \
    asm volatile("mma.sync.aligned.m16n8k16.row.col.f16.f16.f16.f16 " \
        "{%0,%1},{%2,%3,%4,%5},{%6,%7},{%0,%1};" \
        : "+r"((d)[0]),"+r"((d)[1]) \
        : "r"((a)[0]),"r"((a)[1]),"r"((a)[2]),"r"((a)[3]), "r"(b0),"r"(b1))

__device__ __forceinline__ uint32_t f2h2(float x, float y){
    __half2 h = __floats2half2_rn(x, y);
    return *(uint32_t*)&h;
}
__device__ __forceinline__ void split_pair_h(float x, float y, uint32_t& h2, uint32_t& l2){
    h2 = f2h2(x, y);
    float2 f = __half22float2(*(__half2*)&h2);
    l2 = f2h2(x - f.x, y - f.y);
}
// fast e^x on FMA/ALU pipes. valid for x <= 0, clamps below -87. fast_exp(0)==1.0f exactly.
__device__ __forceinline__ float fast_exp(float x){
    x = fmaxf(x, -87.0f);
    float y = x * 1.4426950408889634f;
    float r = __fadd_rn(y, 12582912.0f);
    float f = y - __fadd_rn(r, -12582912.0f);
    float p = 1.5403530e-4f;
    p = __fmaf_rn(p, f, 1.3333558e-3f);
    p = __fmaf_rn(p, f, 9.6181291e-3f);
    p = __fmaf_rn(p, f, 5.5504109e-2f);
    p = __fmaf_rn(p, f, 2.4022651e-1f);
    p = __fmaf_rn(p, f, 6.9314718e-1f);
    p = __fmaf_rn(p, f, 1.0f);
    int n = __float_as_int(r) - 0x4B400000;
    return __int_as_float(__float_as_int(p) + (n << 23));
}

// ---------------- fused preprocessing: rope tables + hs split + weight cvt ---
#define PRE_ROPE_BLKS 64
#define PRE_HS_BLKS   (TOK*H_/2048)                       // 8192
#define PRE_W_BLKS    ((QWN + 2*KWN + H_*H_)/2048)        // 20480
#define PRE_BLKS      (PRE_ROPE_BLKS + PRE_HS_BLKS + PRE_W_BLKS)

__global__ void preproc_kernel(const float* __restrict__ hs,
                               const float* __restrict__ Wq, const float* __restrict__ Wk,
                               const float* __restrict__ Wv, const float* __restrict__ Wo){
    int blk = blockIdx.x;
    if (blk < PRE_ROPE_BLKS){
        int idx0 = (blk << 11) + (threadIdx.x << 3);
        #pragma unroll
        for (int u = 0; u < 8; ++u){
            int idx = idx0 + u;
            int s = idx >> 6, j = idx & 63;
            double inv = pow(500000.0, -((double)j)/64.0);
            float ang = (float)s * (float)inv;
            g_cos[idx] = (float)cos((double)ang);
            g_sin[idx] = (float)sin((double)ang);
        }
        return;
    }
    blk -= PRE_ROPE_BLKS;
    if (blk < PRE_HS_BLKS){
        size_t i = (((size_t)blk << 8) + threadIdx.x) << 3;
        #pragma unroll
        for (int u = 0; u < 2; ++u){
            float4 v = *(const float4*)(hs + i + u*4);
            uint32_t h0, l0, h1, l1;
            split_pair_h(v.x, v.y, h0, l0);
            split_pair_h(v.z, v.w, h1, l1);
            *(uint32_t*)(g_hsH + i + u*4)     = h0;
            *(uint32_t*)(g_hsH + i + u*4 + 2) = h1;
            *(uint32_t*)(g_hsL + i + u*4)     = l0;
            *(uint32_t*)(g_hsL + i + u*4 + 2) = l1;
        }
        return;
    }
    blk -= PRE_HS_BLKS;
    size_t i = (((size_t)blk << 8) + threadIdx.x) << 3;
    const float* src; __half* dst; size_t off;
    if (i < QWN)              { src = Wq; dst = g_Wq; off = i; }
    else if (i < QWN + KWN)   { src = Wk; dst = g_Wk; off = i - QWN; }
    else if (i < QWN + 2*KWN) { src = Wv; dst = g_Wv; off = i - QWN - KWN; }
    else                      { src = Wo; dst = g_Wo; off = i - QWN - 2*KWN; }
    #pragma unroll
    for (int u = 0; u < 2; ++u){
        float4 v = *(const float4*)(src + off + u*4);
        *(uint32_t*)(dst + off + u*4)     = f2h2(v.x, v.y);
        *(uint32_t*)(dst + off + u*4 + 2) = f2h2(v.z, v.w);
    }
}

// ---------------- HMMA GEMM (fused QKV 2-pass / O-proj 1-pass) ---------------
// BM=128 BN=128 BK=64; 8 warps (4x2); 2-stage cp.async; 2 CTAs/SM.
#define BK_      64
#define ROWB     144
#define MATB     (128*ROWB)             // 18432
#define STGB     (3*MATB)               // 55296 (AH, AL, BH)
#define GSMEM    (2*STGB)               // 110592
#define KTILES   (H_/BK_)               // 64

__device__ __forceinline__ void hmma_load_stage(
    uint32_t sb, int s, const __half* AH, const __half* AL, const __half* BH,
    int M0, int N0, int kt, int tid, int twoPass)
{
    uint32_t base = sb + s*STGB;
    #pragma unroll
    for (int i = 0; i < 12; ++i){
        int c = tid + (i << 8);
        int mat = c >> 10;
        if (mat == 1 && !twoPass) continue;
        int cc = c & 1023;
        int row = cc >> 3, ch = cc & 7;
        uint32_t soff = (uint32_t)mat*MATB + row*ROWB + (ch << 4);
        const __half* src = (mat == 0) ? AH : (mat == 1) ? AL : BH;
        int base_row = (mat == 2) ? N0 : M0;
        CP_ASYNC16(base + soff, src + (size_t)(base_row + row)*H_ + kt*BK_ + (ch << 3));
    }
}

// mode 0: fused QKV projections (blockIdx.x: 0-31 Q, 32-39 K, 40-47 V), 2-pass
// mode 1: O projection -> Cout fp32, single-pass (OH only)
__global__ __launch_bounds__(256, 2)
void gemm_hmma_kernel(float* __restrict__ Cout, int mode)
{
    extern __shared__ char smem[];
    uint32_t sb = smem_to_u32(smem);
    const int tid = threadIdx.x;
    const int wid = tid >> 5, lane = tid & 31;
    const int wm = wid & 3, wn = wid >> 2;
    const int bx = blockIdx.x;
    const int M0 = blockIdx.y << 7;
    const int twoPass = (mode == 0);

    const __half *AH, *AL, *BH;
    int N0, dest, head = 0;
    if (mode == 1){
        AH = g_OH; AL = g_OH; BH = g_Wo;
        N0 = bx << 7; dest = 3;
    } else {
        AH = g_hsH; AL = g_hsL;
        if (bx < 32)      { BH = g_Wq; head = bx;      dest = 0; }
        else if (bx < 40) { BH = g_Wk; head = bx - 32; dest = 1; }
        else              { BH = g_Wv; head = bx - 40; dest = 2; }
        N0 = head << 7;
    }

    float acc[2][8][4];
    #pragma unroll
    for (int m = 0; m < 2; ++m)
        #pragma unroll
        for (int n = 0; n < 8; ++n)
            #pragma unroll
            for (int j = 0; j < 4; ++j) acc[m][n][j] = 0.f;

    hmma_load_stage(sb, 0, AH, AL, BH, M0, N0, 0, tid, twoPass); CP_COMMIT();

    const uint32_t aRow = (uint32_t)(wm*32 + (lane & 15));
    const uint32_t aColB = (uint32_t)(((lane >> 4) << 3) * 2);
    const uint32_t bRow = (uint32_t)(wn*64 + ((lane & 7) | ((lane & 16) >> 1)));
    const uint32_t bColB = (uint32_t)((((lane >> 3) & 1) << 3) * 2);

    #pragma unroll 1
    for (int kt = 0; kt < KTILES; ++kt){
        const int s = kt & 1;
        CP_WAIT0();
        __syncthreads();
        if (kt + 1 < KTILES){
            hmma_load_stage(sb, s^1, AH, AL, BH, M0, N0, kt + 1, tid, twoPass);
            CP_COMMIT();
        }

        const uint32_t stA = sb + s*STGB;
        const uint32_t stB = stA + 2*MATB;
        #pragma unroll
        for (int ks = 0; ks < 4; ++ks){
            const uint32_t kB = (uint32_t)(ks << 5);
            uint32_t aHr[2][4], aLr[2][4];
            #pragma unroll
            for (int mm = 0; mm < 2; ++mm){
                uint32_t off = (aRow + mm*16)*ROWB + kB + aColB;
                LDSM_X4(aHr[mm], stA + off);
                if (twoPass) LDSM_X4(aLr[mm], stA + MATB + off);
            }
            #pragma unroll
            for (int g = 0; g < 4; ++g){
                uint32_t bH[4];
                uint32_t off = (bRow + g*16)*ROWB + kB + bColB;
                LDSM_X4(bH, stB + off);
                MMA_F16(acc[0][2*g],   aHr[0], bH[0], bH[1]);
                MMA_F16(acc[0][2*g+1], aHr[0], bH[2], bH[3]);
                MMA_F16(acc[1][2*g],   aHr[1], bH[0], bH[1]);
                MMA_F16(acc[1][2*g+1], aHr[1], bH[2], bH[3]);
                if (twoPass){
                    MMA_F16(acc[0][2*g],   aLr[0], bH[0], bH[1]);
                    MMA_F16(acc[0][2*g+1], aLr[0], bH[2], bH[3]);
                    MMA_F16(acc[1][2*g],   aLr[1], bH[0], bH[1]);
                    MMA_F16(acc[1][2*g+1], aLr[1], bH[2], bH[3]);
                }
            }
        }
    }

    // ---- epilogue ----
    const int rbase = wm*32 + (lane >> 2);
    const int cbase = wn*64 + (lane & 3)*2;
    if (dest == 3 || dest == 2){
        #pragma unroll
        for (int mm = 0; mm < 2; ++mm){
            #pragma unroll
            for (int half = 0; half < 2; ++half){
                int r = M0 + rbase + mm*16 + half*8;
                #pragma unroll
                for (int nn = 0; nn < 8; ++nn){
                    float vx = acc[mm][nn][half*2];
                    float vy = acc[mm][nn][half*2 + 1];
                    if (dest == 3){
                        float2 v; v.x = vx; v.y = vy;
                        *(float2*)(Cout + (size_t)r*H_ + N0 + cbase + nn*8) = v;
                    } else {
                        int bb = r >> 11, ss = r & (S_ - 1);
                        size_t idx = (((size_t)bb*NKV_ + head)*S_ + ss)*HD_ + cbase + nn*8;
                        *(uint32_t*)(g_Vb + idx) = f2h2(vx, vy);
                    }
                }
            }
        }
    } else {
        __syncthreads();
        float* sm32 = (float*)smem;
        #pragma unroll
        for (int mm = 0; mm < 2; ++mm){
            #pragma unroll
            for (int half = 0; half < 2; ++half){
                int rl = rbase + mm*16 + half*8;
                #pragma unroll
                for (int nn = 0; nn < 8; ++nn){
                    float2 v;
                    v.x = acc[mm][nn][half*2];
                    v.y = acc[mm][nn][half*2 + 1];
                    *(float2*)(sm32 + rl*132 + cbase + nn*8) = v;
                }
            }
        }
        __syncthreads();
        const float qsc = 0.08838834764831845f;
        #pragma unroll 4
        for (int i = tid; i < 128*32; i += 256){
            int r = i >> 5, jp = (i & 31) << 1;
            int token = M0 + r;
            int bb = token >> 11, ss = token & (S_ - 1);
            float ca = g_cos[(ss << 6) + jp],     sa = g_sin[(ss << 6) + jp];
            float cb = g_cos[(ss << 6) + jp + 1], sb2 = g_sin[(ss << 6) + jp + 1];
            float x1a = sm32[r*132 + jp],      x1b = sm32[r*132 + jp + 1];
            float x2a = sm32[r*132 + jp + 64], x2b = sm32[r*132 + jp + 65];
            float y1a = x1a*ca - x2a*sa,  y1b = x1b*cb - x2b*sb2;
            float y2a = x2a*ca + x1a*sa,  y2b = x2b*cb + x1b*sb2;
            if (dest == 0){
                y1a *= qsc; y1b *= qsc; y2a *= qsc; y2b *= qsc;
                size_t base = (((size_t)bb*NH_ + head)*S_ + ss)*HD_;
                uint32_t h2a, l2a, h2b, l2b;
                split_pair_h(y1a, y1b, h2a, l2a);
                split_pair_h(y2a, y2b, h2b, l2b);
                *(uint32_t*)(g_QbH + base + jp)      = h2a;
                *(uint32_t*)(g_QbH + base + jp + 64) = h2b;
                *(uint32_t*)(g_QbL + base + jp)      = l2a;
                *(uint32_t*)(g_QbL + base + jp + 64) = l2b;
            } else {
                size_t base = (((size_t)bb*NKV_ + head)*S_ + ss)*HD_;
                *(uint32_t*)(g_Kb + base + jp)      = f2h2(y1a, y1b);
                *(uint32_t*)(g_Kb + base + jp + 64) = f2h2(y2a, y2b);
            }
        }
    }
}

// ---------------- HMMA flash attention (2-stage 32-key KV, single-pass PV) --
#define AROWB 272
#define AQMAT (128*AROWB)               // 34816
#define AKMAT (32*AROWB)                // 8704
#define ASTGB (2*AKMAT)                 // 17408
#define ASMEM (2*AQMAT + 2*ASTGB)       // 104448 -> 2 CTAs/SM
#define NKB   (S_/32)                   // 64

__device__ __forceinline__ void attn_load_kv(
    uint32_t st, const __half* Kg, const __half* Vg, int key0, int tid)
{
    #pragma unroll
    for (int i = 0; i < 4; ++i){
        int c = tid + (i << 8);
        int mat = c >> 9;
        int cc = c & 511;
        int row = cc >> 4, ch = cc & 15;
        uint32_t dst = st + (uint32_t)mat*AKMAT + row*AROWB + (ch << 4);
        const __half* src = mat ? Vg : Kg;
        CP_ASYNC16(dst, src + (size_t)(key0 + row)*HD_ + (ch << 3));
    }
}

__global__ __launch_bounds__(256, 2)
void attn_mma_kernel(){
    extern __shared__ char smem[];
    uint32_t sb = smem_to_u32(smem);
    const int tid = threadIdx.x;
    const int wid = tid >> 5, lane = tid & 31;
    const int qb = blockIdx.x, h = blockIdx.y, b = blockIdx.z;
    const int g = h >> 2;

    const __half* QHg = g_QbH + (((size_t)b*NH_ + h)*S_ + (size_t)qb*128)*HD_;
    const __half* QLg = g_QbL + (((size_t)b*NH_ + h)*S_ + (size_t)qb*128)*HD_;
    const __half* Kg  = g_Kb + ((size_t)b*NKV_ + g)*S_*HD_;
    const __half* Vg  = g_Vb + ((size_t)b*NKV_ + g)*S_*HD_;

    const uint32_t QH0 = sb, QL0 = sb + AQMAT;
    const uint32_t KVB = sb + 2*AQMAT;

    #pragma unroll
    for (int i = 0; i < 16; ++i){
        int c = tid + (i << 8);
        int mat = c >> 11;
        int cc = c & 2047;
        int row = cc >> 4, ch = cc & 15;
        uint32_t dst = (mat ? QL0 : QH0) + row*AROWB + (ch << 4);
        const __half* src = mat ? QLg : QHg;
        CP_ASYNC16(dst, src + (size_t)row*HD_ + (ch << 3));
    }
    attn_load_kv(KVB, Kg, Vg, 0, tid);
    CP_COMMIT();

    float m0 = -1e30f, m1 = -1e30f, l0 = 0.f, l1 = 0.f;
    float O[16][4];
    #pragma unroll
    for (int nt = 0; nt < 16; ++nt)
        #pragma unroll
        for (int j = 0; j < 4; ++j) O[nt][j] = 0.f;

    const uint32_t aOff  = (uint32_t)(wid*16 + (lane & 15))*AROWB + ((lane >> 4) << 4);
    const uint32_t bOffK = (uint32_t)((lane & 7) | ((lane & 16) >> 1))*AROWB + (((lane >> 3) & 1) << 4);
    const uint32_t vOff  = (uint32_t)((lane & 7) + (lane & 8))*AROWB + ((lane >> 4) << 4);

    #pragma unroll 1
    for (int kb = 0; kb < NKB; ++kb){
        const int s = kb & 1;
        const uint32_t Kst = KVB + s*ASTGB;
        const uint32_t Vst = Kst + AKMAT;

        CP_WAIT0();
        __syncthreads();
        if (kb + 1 < NKB){
            attn_load_kv(KVB + (s^1)*ASTGB, Kg, Vg, (kb+1)*32, tid);
            CP_COMMIT();
        }

        // ---- S = Q K^T: hi pass fp32-acc, lo pass f16-acc (folded after) ----
        float Sa[4][4];
        uint32_t SaLo[4][2];
        #pragma unroll
        for (int nt = 0; nt < 4; ++nt){
            #pragma unroll
            for (int j = 0; j < 4; ++j) Sa[nt][j] = 0.f;
            SaLo[nt][0] = 0u; SaLo[nt][1] = 0u;
        }

        #pragma unroll
        for (int ks = 0; ks < 8; ++ks){
            uint32_t aH[4], aL[4];
            LDSM_X4(aH, QH0 + aOff + ks*32);
            LDSM_X4(aL, QL0 + aOff + ks*32);
            #pragma unroll
            for (int gi = 0; gi < 2; ++gi){
                uint32_t bK[4];
                LDSM_X4(bK, Kst + bOffK + gi*(16*AROWB) + ks*32);
                MMA_F16(Sa[2*gi],   aH, bK[0], bK[1]);
                MMA_F16(Sa[2*gi+1], aH, bK[2], bK[3]);
                MMA_F16ACC(SaLo[2*gi],   aL, bK[0], bK[1]);
                MMA_F16ACC(SaLo[2*gi+1], aL, bK[2], bK[3]);
            }
        }
        #pragma unroll
        for (int nt = 0; nt < 4; ++nt){
            float2 lo0 = __half22float2(*(__half2*)&SaLo[nt][0]);
            float2 lo1 = __half22float2(*(__half2*)&SaLo[nt][1]);
            Sa[nt][0] += lo0.x; Sa[nt][1] += lo0.y;
            Sa[nt][2] += lo1.x; Sa[nt][3] += lo1.y;
        }

        // ---- online softmax ----
        float mb0 = -1e30f, mb1 = -1e30f;
        #pragma unroll
        for (int nt = 0; nt < 4; ++nt){
            mb0 = fmaxf(mb0, fmaxf(Sa[nt][0], Sa[nt][1]));
            mb1 = fmaxf(mb1, fmaxf(Sa[nt][2], Sa[nt][3]));
        }
        mb0 = fmaxf(mb0, __shfl_xor_sync(0xffffffffu, mb0, 1));
        mb0 = fmaxf(mb0, __shfl_xor_sync(0xffffffffu, mb0, 2));
        mb1 = fmaxf(mb1, __shfl_xor_sync(0xffffffffu, mb1, 1));
        mb1 = fmaxf(mb1, __shfl_xor_sync(0xffffffffu, mb1, 2));
        float m0n = fmaxf(m0, mb0), m1n = fmaxf(m1, mb1);
        float corr0 = fast_exp(m0 - m0n), corr1 = fast_exp(m1 - m1n);
        m0 = m0n; m1 = m1n;

        float ls0 = 0.f, ls1 = 0.f;
        #pragma unroll
        for (int nt = 0; nt < 4; ++nt){
            Sa[nt][0] = fast_exp(Sa[nt][0] - m0);
            Sa[nt][1] = fast_exp(Sa[nt][1] - m0);
            Sa[nt][2] = fast_exp(Sa[nt][2] - m1);
            Sa[nt][3] = fast_exp(Sa[nt][3] - m1);
            ls0 += Sa[nt][0] + Sa[nt][1];
            ls1 += Sa[nt][2] + Sa[nt][3];
        }
        ls0 += __shfl_xor_sync(0xffffffffu, ls0, 1);
        ls0 += __shfl_xor_sync(0xffffffffu, ls0, 2);
        ls1 += __shfl_xor_sync(0xffffffffu, ls1, 1);
        ls1 += __shfl_xor_sync(0xffffffffu, ls1, 2);
        l0 = l0*corr0 + ls0;
        l1 = l1*corr1 + ls1;

        if (!__all_sync(0xffffffffu, (corr0 == 1.0f) && (corr1 == 1.0f))){
            #pragma unroll
            for (int nt = 0; nt < 16; ++nt){
                O[nt][0] *= corr0; O[nt][1] *= corr0;
                O[nt][2] *= corr1; O[nt][3] *= corr1;
            }
        }

        // ---- P -> A fragments (fp16) ----
        uint32_t aP[2][4];
        #pragma unroll
        for (int kt = 0; kt < 2; ++kt){
            aP[kt][0] = f2h2(Sa[2*kt][0],   Sa[2*kt][1]);
            aP[kt][1] = f2h2(Sa[2*kt][2],   Sa[2*kt][3]);
            aP[kt][2] = f2h2(Sa[2*kt+1][0], Sa[2*kt+1][1]);
            aP[kt][3] = f2h2(Sa[2*kt+1][2], Sa[2*kt+1][3]);
        }

        // ---- O += P V (single pass) ----
        #pragma unroll
        for (int kt = 0; kt < 2; ++kt){
            #pragma unroll
            for (int dp = 0; dp < 8; ++dp){
                uint32_t bV[4];
                LDSM_X4_T(bV, Vst + vOff + kt*(16*AROWB) + dp*32);
                MMA_F16(O[2*dp],   aP[kt], bV[0], bV[1]);
                MMA_F16(O[2*dp+1], aP[kt], bV[2], bV[3]);
            }
        }
    }

    // ---- epilogue: normalize, fp16 to g_OH ----
    const float inv0 = 1.0f / l0, inv1 = 1.0f / l1;
    const int s0 = qb*128 + wid*16 + (lane >> 2);
    const size_t ob = (size_t)b*S_*H_ + (size_t)h*HD_;
    #pragma unroll
    for (int nt = 0; nt < 16; ++nt){
        int d = nt*8 + (lane & 3)*2;
        *(uint32_t*)(g_OH + ob + (size_t)s0*H_ + d)       = f2h2(O[nt][0]*inv0, O[nt][1]*inv0);
        *(uint32_t*)(g_OH + ob + (size_t)(s0 + 8)*H_ + d) = f2h2(O[nt][2]*inv1, O[nt][3]*inv1);
    }
}

// ---------------- launch ----------------------------------------------------
extern "C" void kernel_launch(void* const* d_in, const int* in_sizes, int n_in,
                              void* d_out, int out_size)
{
    const float* hs = (const float*)d_in[0];
    const float* Wq = (const float*)d_in[1];
    const float* Wk = (const float*)d_in[2];
    const float* Wv = (const float*)d_in[3];
    const float* Wo = (const float*)d_in[4];
    float* out = (float*)d_out;

    preproc_kernel<<<PRE_BLKS, 256>>>(hs, Wq, Wk, Wv, Wo);

    cudaFuncSetAttribute(gemm_hmma_kernel, cudaFuncAttributeMaxDynamicSharedMemorySize, GSMEM);
    cudaFuncSetAttribute(attn_mma_kernel, cudaFuncAttributeMaxDynamicSharedMemorySize, ASMEM);

    gemm_hmma_kernel<<<dim3(48, 32), 256, GSMEM>>>(nullptr, 0);
    attn_mma_kernel<<<dim3(S_/128, NH_, B_), 256, ASMEM>>>();
    gemm_hmma_kernel<<<dim3(32, 32), 256, GSMEM>>>(out, 1);
}

// round 16
// speedup vs baseline: 1.3981x; 1.1343x over previous
#include <cuda_runtime.h>
#include <cuda_fp16.h>
#include <math.h>
#include <stdint.h>

#define B_   2
#define S_   2048
#define H_   4096
#define NH_  32
#define NKV_ 8
#define HD_  128
#define TOK  (B_*S_)        // 4096
#define QWN  (NH_*HD_*H_)   // 16777216
#define KWN  (NKV_*HD_*H_)  // 4194304

// ---------------- scratch (static device globals; no allocation) ----------
__device__ float g_cos[S_*64];
__device__ float g_sin[S_*64];

// fp16 operands
__device__ __half g_hsH[(size_t)TOK*H_], g_hsL[(size_t)TOK*H_];
__device__ __half g_Wq[(size_t)QWN];
__device__ __half g_Wk[(size_t)KWN];
__device__ __half g_Wv[(size_t)KWN];
__device__ __half g_Wo[(size_t)H_*H_];
__device__ __half g_OH[(size_t)TOK*H_];

// attention operands (fp16; RoPE and scale pre-applied)
__device__ __half g_QbH[(size_t)B_*NH_*S_*HD_], g_QbL[(size_t)B_*NH_*S_*HD_];
__device__ __half g_Kb[(size_t)B_*NKV_*S_*HD_];
__device__ __half g_Vb[(size_t)B_*NKV_*S_*HD_];

// ---------------- helpers ----------------------------------------------------
__device__ __forceinline__ uint32_t smem_to_u32(const void* p){
    uint32_t a;
    asm("{ .reg .u64 t; cvta.to.shared.u64 t, %1; cvt.u32.u64 %0, t; }" : "=r"(a) : "l"(p));
    return a;
}
#define CP_ASYNC16(dst, src) \
    asm volatile("cp.async.cg.shared.global [%0], [%1], 16;" :: "r"(dst), "l"(src))
#define CP_COMMIT() asm volatile("cp.async.commit_group;" ::: "memory")
#define CP_WAIT1()  asm volatile("cp.async.wait_group 1;" ::: "memory")
#define CP_WAIT0()  asm volatile("cp.async.wait_group 0;" ::: "memory")

#define LDSM_X4(r, addr) \
    asm volatile("ldmatrix.sync.aligned.m8n8.x4.shared.b16 {%0,%1,%2,%3}, [%4];" \
        : "=r"((r)[0]),"=r"((r)[1]),"=r"((r)[2]),"=r"((r)[3]) : "r"(addr))
#define LDSM_X4_T(r, addr) \
    asm volatile("ldmatrix.sync.aligned.m8n8.x4.trans.shared.b16 {%0,%1,%2,%3}, [%4];" \
        : "=r"((r)[0]),"=r"((r)[1]),"=r"((r)[2]),"=r"((r)[3]) : "r"(addr))

#define MMA_F16(c, a, b0, b1) \
    asm volatile("mma.sync.aligned.m16n8k16.row.col.f32.f16.f16.f32 " \
        "{%0,%1,%2,%3},{%4,%5,%6,%7},{%8,%9},{%0,%1,%2,%3};" \
        : "+f"((c)[0]),"+f"((c)[1]),"+f"((c)[2]),"+f"((c)[3]) \
        : "r"((a)[0]),"r"((a)[1]),"r"((a)[2]),"r"((a)[3]), "r"(b0),"r"(b1))

// f16-accumulator HMMA
#define MMA_F16ACC(d, a, b0, b1) \
    asm volatile("mma.sync.aligned.m16n8k16.row.col.f16.f16.f16.f16 " \
        "{%0,%1},{%2,%3,%4,%5},{%6,%7},{%0,%1};" \
        : "+r"((d)[0]),"+r"((d)[1]) \
        : "r"((a)[0]),"r"((a)[1]),"r"((a)[2]),"r"((a)[3]), "r"(b0),"r"(b1))

__device__ __forceinline__ uint32_t f2h2(float x, float y){
    __half2 h = __floats2half2_rn(x, y);
    return *(uint32_t*)&h;
}
__device__ __forceinline__ void split_pair_h(float x, float y, uint32_t& h2, uint32_t& l2){
    h2 = f2h2(x, y);
    float2 f = __half22float2(*(__half2*)&h2);
    l2 = f2h2(x - f.x, y - f.y);
}
// fast e^x on FMA/ALU pipes. valid for x <= 0, clamps below -87. fast_exp(0)==1.0f exactly.
__device__ __forceinline__ float fast_exp(float x){
    x = fmaxf(x, -87.0f);
    float y = x * 1.4426950408889634f;
    float r = __fadd_rn(y, 12582912.0f);
    float f = y - __fadd_rn(r, -12582912.0f);
    float p = 1.5403530e-4f;
    p = __fmaf_rn(p, f, 1.3333558e-3f);
    p = __fmaf_rn(p, f, 9.6181291e-3f);
    p = __fmaf_rn(p, f, 5.5504109e-2f);
    p = __fmaf_rn(p, f, 2.4022651e-1f);
    p = __fmaf_rn(p, f, 6.9314718e-1f);
    p = __fmaf_rn(p, f, 1.0f);
    int n = __float_as_int(r) - 0x4B400000;
    return __int_as_float(__float_as_int(p) + (n << 23));
}

// ---------------- fused preprocessing: rope tables + hs split + weight cvt ---
#define PRE_ROPE_BLKS 64
#define PRE_HS_BLKS   (TOK*H_/2048)                       // 8192
#define PRE_W_BLKS    ((QWN + 2*KWN + H_*H_)/2048)        // 20480
#define PRE_BLKS      (PRE_ROPE_BLKS + PRE_HS_BLKS + PRE_W_BLKS)

__global__ void preproc_kernel(const float* __restrict__ hs,
                               const float* __restrict__ Wq, const float* __restrict__ Wk,
                               const float* __restrict__ Wv, const float* __restrict__ Wo){
    int blk = blockIdx.x;
    if (blk < PRE_ROPE_BLKS){
        int idx0 = (blk << 11) + (threadIdx.x << 3);
        #pragma unroll
        for (int u = 0; u < 8; ++u){
            int idx = idx0 + u;
            int s = idx >> 6, j = idx & 63;
            double inv = pow(500000.0, -((double)j)/64.0);
            float ang = (float)s * (float)inv;
            g_cos[idx] = (float)cos((double)ang);
            g_sin[idx] = (float)sin((double)ang);
        }
        return;
    }
    blk -= PRE_ROPE_BLKS;
    if (blk < PRE_HS_BLKS){
        size_t i = (((size_t)blk << 8) + threadIdx.x) << 3;
        #pragma unroll
        for (int u = 0; u < 2; ++u){
            float4 v = *(const float4*)(hs + i + u*4);
            uint32_t h0, l0, h1, l1;
            split_pair_h(v.x, v.y, h0, l0);
            split_pair_h(v.z, v.w, h1, l1);
            *(uint32_t*)(g_hsH + i + u*4)     = h0;
            *(uint32_t*)(g_hsH + i + u*4 + 2) = h1;
            *(uint32_t*)(g_hsL + i + u*4)     = l0;
            *(uint32_t*)(g_hsL + i + u*4 + 2) = l1;
        }
        return;
    }
    blk -= PRE_HS_BLKS;
    size_t i = (((size_t)blk << 8) + threadIdx.x) << 3;
    const float* src; __half* dst; size_t off;
    if (i < QWN)              { src = Wq; dst = g_Wq; off = i; }
    else if (i < QWN + KWN)   { src = Wk; dst = g_Wk; off = i - QWN; }
    else if (i < QWN + 2*KWN) { src = Wv; dst = g_Wv; off = i - QWN - KWN; }
    else                      { src = Wo; dst = g_Wo; off = i - QWN - 2*KWN; }
    #pragma unroll
    for (int u = 0; u < 2; ++u){
        float4 v = *(const float4*)(src + off + u*4);
        *(uint32_t*)(dst + off + u*4)     = f2h2(v.x, v.y);
        *(uint32_t*)(dst + off + u*4 + 2) = f2h2(v.z, v.w);
    }
}

// ---------------- HMMA QKV GEMM (Q 2-pass; K/V single-pass) ------------------
// BM=128 BN=128 BK=64; 8 warps (4x2); 2-stage cp.async; 2 CTAs/SM.
#define BK_      64
#define ROWB     144
#define MATB     (128*ROWB)             // 18432
#define STGB     (3*MATB)               // 55296 (AH, AL, BH)
#define GSMEM    (2*STGB)               // 110592
#define KTILES   (H_/BK_)               // 64

__device__ __forceinline__ void hmma_load_stage(
    uint32_t sb, int s, const __half* AH, const __half* AL, const __half* BH,
    int M0, int N0, int kt, int tid, int twoPass)
{
    uint32_t base = sb + s*STGB;
    #pragma unroll
    for (int i = 0; i < 12; ++i){
        int c = tid + (i << 8);
        int mat = c >> 10;
        if (mat == 1 && !twoPass) continue;
        int cc = c & 1023;
        int row = cc >> 3, ch = cc & 7;
        uint32_t soff = (uint32_t)mat*MATB + row*ROWB + (ch << 4);
        const __half* src = (mat == 0) ? AH : (mat == 1) ? AL : BH;
        int base_row = (mat == 2) ? N0 : M0;
        CP_ASYNC16(base + soff, src + (size_t)(base_row + row)*H_ + kt*BK_ + (ch << 3));
    }
}

// blockIdx.x: 0-31 Q (2-pass), 32-39 K (1-pass), 40-47 V (1-pass)
__global__ __launch_bounds__(256, 2)
void gemm_qkv_kernel()
{
    extern __shared__ char smem[];
    uint32_t sb = smem_to_u32(smem);
    const int tid = threadIdx.x;
    const int wid = tid >> 5, lane = tid & 31;
    const int wm = wid & 3, wn = wid >> 2;
    const int bx = blockIdx.x;
    const int M0 = blockIdx.y << 7;
    const int twoPass = (bx < 32);

    const __half *AH = g_hsH, *AL = g_hsL, *BH;
    int dest, head;
    if (bx < 32)      { BH = g_Wq; head = bx;      dest = 0; }
    else if (bx < 40) { BH = g_Wk; head = bx - 32; dest = 1; }
    else              { BH = g_Wv; head = bx - 40; dest = 2; }
    const int N0 = head << 7;

    float acc[2][8][4];
    #pragma unroll
    for (int m = 0; m < 2; ++m)
        #pragma unroll
        for (int n = 0; n < 8; ++n)
            #pragma unroll
            for (int j = 0; j < 4; ++j) acc[m][n][j] = 0.f;

    hmma_load_stage(sb, 0, AH, AL, BH, M0, N0, 0, tid, twoPass); CP_COMMIT();

    const uint32_t aRow = (uint32_t)(wm*32 + (lane & 15));
    const uint32_t aColB = (uint32_t)(((lane >> 4) << 3) * 2);
    const uint32_t bRow = (uint32_t)(wn*64 + ((lane & 7) | ((lane & 16) >> 1)));
    const uint32_t bColB = (uint32_t)((((lane >> 3) & 1) << 3) * 2);

    #pragma unroll 1
    for (int kt = 0; kt < KTILES; ++kt){
        const int s = kt & 1;
        CP_WAIT0();
        __syncthreads();
        if (kt + 1 < KTILES){
            hmma_load_stage(sb, s^1, AH, AL, BH, M0, N0, kt + 1, tid, twoPass);
            CP_COMMIT();
        }

        const uint32_t stA = sb + s*STGB;
        const uint32_t stB = stA + 2*MATB;
        #pragma unroll
        for (int ks = 0; ks < 4; ++ks){
            const uint32_t kB = (uint32_t)(ks << 5);
            uint32_t aHr[2][4], aLr[2][4];
            #pragma unroll
            for (int mm = 0; mm < 2; ++mm){
                uint32_t off = (aRow + mm*16)*ROWB + kB + aColB;
                LDSM_X4(aHr[mm], stA + off);
                if (twoPass) LDSM_X4(aLr[mm], stA + MATB + off);
            }
            #pragma unroll
            for (int g = 0; g < 4; ++g){
                uint32_t bH[4];
                uint32_t off = (bRow + g*16)*ROWB + kB + bColB;
                LDSM_X4(bH, stB + off);
                MMA_F16(acc[0][2*g],   aHr[0], bH[0], bH[1]);
                MMA_F16(acc[0][2*g+1], aHr[0], bH[2], bH[3]);
                MMA_F16(acc[1][2*g],   aHr[1], bH[0], bH[1]);
                MMA_F16(acc[1][2*g+1], aHr[1], bH[2], bH[3]);
                if (twoPass){
                    MMA_F16(acc[0][2*g],   aLr[0], bH[0], bH[1]);
                    MMA_F16(acc[0][2*g+1], aLr[0], bH[2], bH[3]);
                    MMA_F16(acc[1][2*g],   aLr[1], bH[0], bH[1]);
                    MMA_F16(acc[1][2*g+1], aLr[1], bH[2], bH[3]);
                }
            }
        }
    }

    // ---- epilogue ----
    const int rbase = wm*32 + (lane >> 2);
    const int cbase = wn*64 + (lane & 3)*2;
    if (dest == 2){
        #pragma unroll
        for (int mm = 0; mm < 2; ++mm){
            #pragma unroll
            for (int half = 0; half < 2; ++half){
                int r = M0 + rbase + mm*16 + half*8;
                #pragma unroll
                for (int nn = 0; nn < 8; ++nn){
                    int bb = r >> 11, ss = r & (S_ - 1);
                    size_t idx = (((size_t)bb*NKV_ + head)*S_ + ss)*HD_ + cbase + nn*8;
                    *(uint32_t*)(g_Vb + idx) = f2h2(acc[mm][nn][half*2], acc[mm][nn][half*2 + 1]);
                }
            }
        }
    } else {
        __syncthreads();
        float* sm32 = (float*)smem;
        #pragma unroll
        for (int mm = 0; mm < 2; ++mm){
            #pragma unroll
            for (int half = 0; half < 2; ++half){
                int rl = rbase + mm*16 + half*8;
                #pragma unroll
                for (int nn = 0; nn < 8; ++nn){
                    float2 v;
                    v.x = acc[mm][nn][half*2];
                    v.y = acc[mm][nn][half*2 + 1];
                    *(float2*)(sm32 + rl*132 + cbase + nn*8) = v;
                }
            }
        }
        __syncthreads();
        const float qsc = 0.08838834764831845f;
        #pragma unroll 4
        for (int i = tid; i < 128*32; i += 256){
            int r = i >> 5, jp = (i & 31) << 1;
            int token = M0 + r;
            int bb = token >> 11, ss = token & (S_ - 1);
            float ca = g_cos[(ss << 6) + jp],     sa = g_sin[(ss << 6) + jp];
            float cb = g_cos[(ss << 6) + jp + 1], sb2 = g_sin[(ss << 6) + jp + 1];
            float x1a = sm32[r*132 + jp],      x1b = sm32[r*132 + jp + 1];
            float x2a = sm32[r*132 + jp + 64], x2b = sm32[r*132 + jp + 65];
            float y1a = x1a*ca - x2a*sa,  y1b = x1b*cb - x2b*sb2;
            float y2a = x2a*ca + x1a*sa,  y2b = x2b*cb + x1b*sb2;
            if (dest == 0){
                y1a *= qsc; y1b *= qsc; y2a *= qsc; y2b *= qsc;
                size_t base = (((size_t)bb*NH_ + head)*S_ + ss)*HD_;
                uint32_t h2a, l2a, h2b, l2b;
                split_pair_h(y1a, y1b, h2a, l2a);
                split_pair_h(y2a, y2b, h2b, l2b);
                *(uint32_t*)(g_QbH + base + jp)      = h2a;
                *(uint32_t*)(g_QbH + base + jp + 64) = h2b;
                *(uint32_t*)(g_QbL + base + jp)      = l2a;
                *(uint32_t*)(g_QbL + base + jp + 64) = l2b;
            } else {
                size_t base = (((size_t)bb*NKV_ + head)*S_ + ss)*HD_;
                *(uint32_t*)(g_Kb + base + jp)      = f2h2(y1a, y1b);
                *(uint32_t*)(g_Kb + base + jp + 64) = f2h2(y2a, y2b);
            }
        }
    }
}

// ---------------- HMMA O-projection: single-pass, 3-stage pipeline ----------
#define STGB_O  (2*MATB)                // 36864 (A, B)
#define GSMEM_O (3*STGB_O)              // 110592 -> 2 CTAs/SM

__device__ __forceinline__ void o_load_stage(
    uint32_t sb, int s, const __half* A, const __half* Bm,
    int M0, int N0, int kt, int tid)
{
    uint32_t base = sb + s*STGB_O;
    #pragma unroll
    for (int i = 0; i < 8; ++i){
        int c = tid + (i << 8);          // 0..2047
        int mat = c >> 10;               // 0=A 1=B
        int cc = c & 1023;
        int row = cc >> 3, ch = cc & 7;
        uint32_t soff = (uint32_t)mat*MATB + row*ROWB + (ch << 4);
        const __half* src = mat ? Bm : A;
        int base_row = mat ? N0 : M0;
        CP_ASYNC16(base + soff, src + (size_t)(base_row + row)*H_ + kt*BK_ + (ch << 3));
    }
}

__global__ __launch_bounds__(256, 2)
void gemm_o_kernel(float* __restrict__ Cout)
{
    extern __shared__ char smem[];
    uint32_t sb = smem_to_u32(smem);
    const int tid = threadIdx.x;
    const int wid = tid >> 5, lane = tid & 31;
    const int wm = wid & 3, wn = wid >> 2;
    const int M0 = blockIdx.y << 7, N0 = blockIdx.x << 7;

    float acc[2][8][4];
    #pragma unroll
    for (int m = 0; m < 2; ++m)
        #pragma unroll
        for (int n = 0; n < 8; ++n)
            #pragma unroll
            for (int j = 0; j < 4; ++j) acc[m][n][j] = 0.f;

    o_load_stage(sb, 0, g_OH, g_Wo, M0, N0, 0, tid); CP_COMMIT();
    o_load_stage(sb, 1, g_OH, g_Wo, M0, N0, 1, tid); CP_COMMIT();

    const uint32_t aRow = (uint32_t)(wm*32 + (lane & 15));
    const uint32_t aColB = (uint32_t)(((lane >> 4) << 3) * 2);
    const uint32_t bRow = (uint32_t)(wn*64 + ((lane & 7) | ((lane & 16) >> 1)));
    const uint32_t bColB = (uint32_t)((((lane >> 3) & 1) << 3) * 2);

    #pragma unroll 1
    for (int kt = 0; kt < KTILES; ++kt){
        const int s = kt % 3;
        if (kt < KTILES - 1) { CP_WAIT1(); } else { CP_WAIT0(); }
        __syncthreads();
        if (kt + 2 < KTILES){
            o_load_stage(sb, (kt + 2) % 3, g_OH, g_Wo, M0, N0, kt + 2, tid);
            CP_COMMIT();
        }

        const uint32_t stA = sb + s*STGB_O;
        const uint32_t stB = stA + MATB;
        #pragma unroll
        for (int ks = 0; ks < 4; ++ks){
            const uint32_t kB = (uint32_t)(ks << 5);
            uint32_t aR[2][4];
            #pragma unroll
            for (int mm = 0; mm < 2; ++mm)
                LDSM_X4(aR[mm], stA + (aRow + mm*16)*ROWB + kB + aColB);
            #pragma unroll
            for (int g = 0; g < 4; ++g){
                uint32_t bH[4];
                LDSM_X4(bH, stB + (bRow + g*16)*ROWB + kB + bColB);
                MMA_F16(acc[0][2*g],   aR[0], bH[0], bH[1]);
                MMA_F16(acc[0][2*g+1], aR[0], bH[2], bH[3]);
                MMA_F16(acc[1][2*g],   aR[1], bH[0], bH[1]);
                MMA_F16(acc[1][2*g+1], aR[1], bH[2], bH[3]);
            }
        }
    }

    const int rbase = M0 + wm*32 + (lane >> 2);
    const int cbase = N0 + wn*64 + (lane & 3)*2;
    #pragma unroll
    for (int mm = 0; mm < 2; ++mm){
        #pragma unroll
        for (int half = 0; half < 2; ++half){
            int r = rbase + mm*16 + half*8;
            #pragma unroll
            for (int nn = 0; nn < 8; ++nn){
                float2 v;
                v.x = acc[mm][nn][half*2];
                v.y = acc[mm][nn][half*2 + 1];
                *(float2*)(Cout + (size_t)r*H_ + cbase + nn*8) = v;
            }
        }
    }
}

// ---------------- HMMA flash attention (2-stage 32-key KV, single-pass PV) --
#define AROWB 272
#define AQMAT (128*AROWB)               // 34816
#define AKMAT (32*AROWB)                // 8704
#define ASTGB (2*AKMAT)                 // 17408
#define ASMEM (2*AQMAT + 2*ASTGB)       // 104448 -> 2 CTAs/SM
#define NKB   (S_/32)                   // 64

__device__ __forceinline__ void attn_load_kv(
    uint32_t st, const __half* Kg, const __half* Vg, int key0, int tid)
{
    #pragma unroll
    for (int i = 0; i < 4; ++i){
        int c = tid + (i << 8);
        int mat = c >> 9;
        int cc = c & 511;
        int row = cc >> 4, ch = cc & 15;
        uint32_t dst = st + (uint32_t)mat*AKMAT + row*AROWB + (ch << 4);
        const __half* src = mat ? Vg : Kg;
        CP_ASYNC16(dst, src + (size_t)(key0 + row)*HD_ + (ch << 3));
    }
}

__global__ __launch_bounds__(256, 2)
void attn_mma_kernel(){
    extern __shared__ char smem[];
    uint32_t sb = smem_to_u32(smem);
    const int tid = threadIdx.x;
    const int wid = tid >> 5, lane = tid & 31;
    const int qb = blockIdx.x, h = blockIdx.y, b = blockIdx.z;
    const int g = h >> 2;

    const __half* QHg = g_QbH + (((size_t)b*NH_ + h)*S_ + (size_t)qb*128)*HD_;
    const __half* QLg = g_QbL + (((size_t)b*NH_ + h)*S_ + (size_t)qb*128)*HD_;
    const __half* Kg  = g_Kb + ((size_t)b*NKV_ + g)*S_*HD_;
    const __half* Vg  = g_Vb + ((size_t)b*NKV_ + g)*S_*HD_;

    const uint32_t QH0 = sb, QL0 = sb + AQMAT;
    const uint32_t KVB = sb + 2*AQMAT;

    #pragma unroll
    for (int i = 0; i < 16; ++i){
        int c = tid + (i << 8);
        int mat = c >> 11;
        int cc = c & 2047;
        int row = cc >> 4, ch = cc & 15;
        uint32_t dst = (mat ? QL0 : QH0) + row*AROWB + (ch << 4);
        const __half* src = mat ? QLg : QHg;
        CP_ASYNC16(dst, src + (size_t)row*HD_ + (ch << 3));
    }
    attn_load_kv(KVB, Kg, Vg, 0, tid);
    CP_COMMIT();

    float m0 = -1e30f, m1 = -1e30f, l0 = 0.f, l1 = 0.f;
    float O[16][4];
    #pragma unroll
    for (int nt = 0; nt < 16; ++nt)
        #pragma unroll
        for (int j = 0; j < 4; ++j) O[nt][j] = 0.f;

    const uint32_t aOff  = (uint32_t)(wid*16 + (lane & 15))*AROWB + ((lane >> 4) << 4);
    const uint32_t bOffK = (uint32_t)((lane & 7) | ((lane & 16) >> 1))*AROWB + (((lane >> 3) & 1) << 4);
    const uint32_t vOff  = (uint32_t)((lane & 7) + (lane & 8))*AROWB + ((lane >> 4) << 4);

    #pragma unroll 1
    for (int kb = 0; kb < NKB; ++kb){
        const int s = kb & 1;
        const uint32_t Kst = KVB + s*ASTGB;
        const uint32_t Vst = Kst + AKMAT;

        CP_WAIT0();
        __syncthreads();
        if (kb + 1 < NKB){
            attn_load_kv(KVB + (s^1)*ASTGB, Kg, Vg, (kb+1)*32, tid);
            CP_COMMIT();
        }

        // ---- S = Q K^T: hi pass fp32-acc, lo pass f16-acc (folded after) ----
        float Sa[4][4];
        uint32_t SaLo[4][2];
        #pragma unroll
        for (int nt = 0; nt < 4; ++nt){
            #pragma unroll
            for (int j = 0; j < 4; ++j) Sa[nt][j] = 0.f;
            SaLo[nt][0] = 0u; SaLo[nt][1] = 0u;
        }

        #pragma unroll
        for (int ks = 0; ks < 8; ++ks){
            uint32_t aH[4], aL[4];
            LDSM_X4(aH, QH0 + aOff + ks*32);
            LDSM_X4(aL, QL0 + aOff + ks*32);
            #pragma unroll
            for (int gi = 0; gi < 2; ++gi){
                uint32_t bK[4];
                LDSM_X4(bK, Kst + bOffK + gi*(16*AROWB) + ks*32);
                MMA_F16(Sa[2*gi],   aH, bK[0], bK[1]);
                MMA_F16(Sa[2*gi+1], aH, bK[2], bK[3]);
                MMA_F16ACC(SaLo[2*gi],   aL, bK[0], bK[1]);
                MMA_F16ACC(SaLo[2*gi+1], aL, bK[2], bK[3]);
            }
        }
        #pragma unroll
        for (int nt = 0; nt < 4; ++nt){
            float2 lo0 = __half22float2(*(__half2*)&SaLo[nt][0]);
            float2 lo1 = __half22float2(*(__half2*)&SaLo[nt][1]);
            Sa[nt][0] += lo0.x; Sa[nt][1] += lo0.y;
            Sa[nt][2] += lo1.x; Sa[nt][3] += lo1.y;
        }

        // ---- online softmax ----
        float mb0 = -1e30f, mb1 = -1e30f;
        #pragma unroll
        for (int nt = 0; nt < 4; ++nt){
            mb0 = fmaxf(mb0, fmaxf(Sa[nt][0], Sa[nt][1]));
            mb1 = fmaxf(mb1, fmaxf(Sa[nt][2], Sa[nt][3]));
        }
        mb0 = fmaxf(mb0, __shfl_xor_sync(0xffffffffu, mb0, 1));
        mb0 = fmaxf(mb0, __shfl_xor_sync(0xffffffffu, mb0, 2));
        mb1 = fmaxf(mb1, __shfl_xor_sync(0xffffffffu, mb1, 1));
        mb1 = fmaxf(mb1, __shfl_xor_sync(0xffffffffu, mb1, 2));
        float m0n = fmaxf(m0, mb0), m1n = fmaxf(m1, mb1);
        float corr0 = fast_exp(m0 - m0n), corr1 = fast_exp(m1 - m1n);
        m0 = m0n; m1 = m1n;

        float ls0 = 0.f, ls1 = 0.f;
        #pragma unroll
        for (int nt = 0; nt < 4; ++nt){
            Sa[nt][0] = fast_exp(Sa[nt][0] - m0);
            Sa[nt][1] = fast_exp(Sa[nt][1] - m0);
            Sa[nt][2] = fast_exp(Sa[nt][2] - m1);
            Sa[nt][3] = fast_exp(Sa[nt][3] - m1);
            ls0 += Sa[nt][0] + Sa[nt][1];
            ls1 += Sa[nt][2] + Sa[nt][3];
        }
        ls0 += __shfl_xor_sync(0xffffffffu, ls0, 1);
        ls0 += __shfl_xor_sync(0xffffffffu, ls0, 2);
        ls1 += __shfl_xor_sync(0xffffffffu, ls1, 1);
        ls1 += __shfl_xor_sync(0xffffffffu, ls1, 2);
        l0 = l0*corr0 + ls0;
        l1 = l1*corr1 + ls1;

        if (!__all_sync(0xffffffffu, (corr0 == 1.0f) && (corr1 == 1.0f))){
            #pragma unroll
            for (int nt = 0; nt < 16; ++nt){
                O[nt][0] *= corr0; O[nt][1] *= corr0;
                O[nt][2] *= corr1; O[nt][3] *= corr1;
            }
        }

        // ---- P -> A fragments (fp16) ----
        uint32_t aP[2][4];
        #pragma unroll
        for (int kt = 0; kt < 2; ++kt){
            aP[kt][0] = f2h2(Sa[2*kt][0],   Sa[2*kt][1]);
            aP[kt][1] = f2h2(Sa[2*kt][2],   Sa[2*kt][3]);
            aP[kt][2] = f2h2(Sa[2*kt+1][0], Sa[2*kt+1][1]);
            aP[kt][3] = f2h2(Sa[2*kt+1][2], Sa[2*kt+1][3]);
        }

        // ---- O += P V (single pass) ----
        #pragma unroll
        for (int kt = 0; kt < 2; ++kt){
            #pragma unroll
            for (int dp = 0; dp < 8; ++dp){
                uint32_t bV[4];
                LDSM_X4_T(bV, Vst + vOff + kt*(16*AROWB) + dp*32);
                MMA_F16(O[2*dp],   aP[kt], bV[0], bV[1]);
                MMA_F16(O[2*dp+1], aP[kt], bV[2], bV[3]);
            }
        }
    }

    // ---- epilogue: normalize, fp16 to g_OH ----
    const float inv0 = 1.0f / l0, inv1 = 1.0f / l1;
    const int s0 = qb*128 + wid*16 + (lane >> 2);
    const size_t ob = (size_t)b*S_*H_ + (size_t)h*HD_;
    #pragma unroll
    for (int nt = 0; nt < 16; ++nt){
        int d = nt*8 + (lane & 3)*2;
        *(uint32_t*)(g_OH + ob + (size_t)s0*H_ + d)       = f2h2(O[nt][0]*inv0, O[nt][1]*inv0);
        *(uint32_t*)(g_OH + ob + (size_t)(s0 + 8)*H_ + d) = f2h2(O[nt][2]*inv1, O[nt][3]*inv1);
    }
}

// ---------------- launch ----------------------------------------------------
extern "C" void kernel_launch(void* const* d_in, const int* in_sizes, int n_in,
                              void* d_out, int out_size)
{
    const float* hs = (const float*)d_in[0];
    const float* Wq = (const float*)d_in[1];
    const float* Wk = (const float*)d_in[2];
    const float* Wv = (const float*)d_in[3];
    const float* Wo = (const float*)d_in[4];
    float* out = (float*)d_out;

    preproc_kernel<<<PRE_BLKS, 256>>>(hs, Wq, Wk, Wv, Wo);

    cudaFuncSetAttribute(gemm_qkv_kernel, cudaFuncAttributeMaxDynamicSharedMemorySize, GSMEM);
    cudaFuncSetAttribute(gemm_o_kernel, cudaFuncAttributeMaxDynamicSharedMemorySize, GSMEM_O);
    cudaFuncSetAttribute(attn_mma_kernel, cudaFuncAttributeMaxDynamicSharedMemorySize, ASMEM);

    gemm_qkv_kernel<<<dim3(48, 32), 256, GSMEM>>>();
    attn_mma_kernel<<<dim3(S_/128, NH_, B_), 256, ASMEM>>>();
    gemm_o_kernel<<<dim3(32, 32), 256, GSMEM_O>>>(out);
}